// round 2
// baseline (speedup 1.0000x reference)
#include <cuda_runtime.h>
#include <cuda_bf16.h>
#include <math.h>

// Problem dims (compile-time)
#define E_  768
#define H_  12
#define D_  64
#define L_  4
#define S_  1024
#define B_  2
#define V_  32000
#define FF_ 4608
#define M_  (B_ * S_)   // 2048 rows

// ---------------- scratch (device globals; no allocations allowed) ----------------
__device__ float g_x  [M_ * E_];
__device__ float g_h  [M_ * E_];
__device__ float g_q  [M_ * E_];
__device__ float g_k  [M_ * E_];
__device__ float g_v  [M_ * E_];
__device__ float g_o  [M_ * E_];
__device__ float g_ff [M_ * FF_];
__device__ float g_attn[(size_t)B_ * H_ * S_ * S_];   // ~100 MB

// ---------------- embedding: x = tok_emb[tok] + pos_emb[s] ----------------
__global__ void embed_kernel(const int* __restrict__ tokens,
                             const float* __restrict__ tok_emb,
                             const float* __restrict__ pos_emb,
                             float* __restrict__ x)
{
    int row = blockIdx.x;            // 0..M_-1
    int s   = row % S_;
    int t   = tokens[row];
    const float4* te = (const float4*)(tok_emb + (size_t)t * E_);
    const float4* pe = (const float4*)(pos_emb + (size_t)s * E_);
    float4*       xo = (float4*)(x + (size_t)row * E_);
    for (int i = threadIdx.x; i < E_ / 4; i += blockDim.x) {
        float4 a = te[i], b = pe[i];
        xo[i] = make_float4(a.x + b.x, a.y + b.y, a.z + b.z, a.w + b.w);
    }
}

// ---------------- layernorm per row ----------------
__global__ void ln_kernel(const float* __restrict__ x,
                          const float* __restrict__ g,
                          const float* __restrict__ b,
                          float* __restrict__ out)
{
    int row = blockIdx.x;
    const float* xr = x + (size_t)row * E_;
    __shared__ float red[256];
    int tid = threadIdx.x;

    float s = 0.f;
    for (int i = tid; i < E_; i += 256) s += xr[i];
    red[tid] = s; __syncthreads();
    for (int o = 128; o > 0; o >>= 1) { if (tid < o) red[tid] += red[tid + o]; __syncthreads(); }
    float mean = red[0] * (1.f / E_);
    __syncthreads();

    float sq = 0.f;
    for (int i = tid; i < E_; i += 256) { float d = xr[i] - mean; sq += d * d; }
    red[tid] = sq; __syncthreads();
    for (int o = 128; o > 0; o >>= 1) { if (tid < o) red[tid] += red[tid + o]; __syncthreads(); }
    float inv = rsqrtf(red[0] * (1.f / E_) + 1e-5f);

    float* orow = out + (size_t)row * E_;
    for (int i = tid; i < E_; i += 256)
        orow[i] = (xr[i] - mean) * inv * g[i] + b[i];
}

// ---------------- generic SGEMM: C = A[M,K] @ B[K,N] (+bias)(+GELU)(+res) ----------------
// Requires M%64==0, N%64==0, K%16==0 (true for all call sites).
template<bool BIAS, bool RES, bool GELU>
__global__ void __launch_bounds__(256)
sgemm_kernel(const float* __restrict__ A, const float* __restrict__ Bm,
             const float* __restrict__ bias, const float* __restrict__ res,
             float* __restrict__ C, int Md, int Nd, int Kd)
{
    const int BM = 64, BN = 64, BK = 16;
    __shared__ float As[BK][BM];
    __shared__ float Bs[BK][BN];

    int tid  = threadIdx.x;
    int row0 = blockIdx.y * BM;
    int col0 = blockIdx.x * BN;
    int tx = tid & 15, ty = tid >> 4;

    int arow = tid >> 2;          // 0..63
    int acol = (tid & 3) * 4;     // 0,4,8,12
    int brow = tid >> 4;          // 0..15
    int bcol = (tid & 15) * 4;    // 0..60

    float acc[4][4] = {};

    for (int k0 = 0; k0 < Kd; k0 += BK) {
        float4 av = *(const float4*)(A + (size_t)(row0 + arow) * Kd + k0 + acol);
        As[acol + 0][arow] = av.x;
        As[acol + 1][arow] = av.y;
        As[acol + 2][arow] = av.z;
        As[acol + 3][arow] = av.w;
        float4 bv = *(const float4*)(Bm + (size_t)(k0 + brow) * Nd + col0 + bcol);
        *(float4*)&Bs[brow][bcol] = bv;
        __syncthreads();

        #pragma unroll
        for (int kk = 0; kk < BK; ++kk) {
            float ar[4], br[4];
            #pragma unroll
            for (int i = 0; i < 4; ++i) ar[i] = As[kk][ty * 4 + i];
            #pragma unroll
            for (int j = 0; j < 4; ++j) br[j] = Bs[kk][tx * 4 + j];
            #pragma unroll
            for (int i = 0; i < 4; ++i)
                #pragma unroll
                for (int j = 0; j < 4; ++j)
                    acc[i][j] += ar[i] * br[j];
        }
        __syncthreads();
    }

    #pragma unroll
    for (int i = 0; i < 4; ++i) {
        int r = row0 + ty * 4 + i;
        #pragma unroll
        for (int j = 0; j < 4; ++j) {
            int c = col0 + tx * 4 + j;
            float v = acc[i][j];
            if (BIAS) v += bias[c];
            if (GELU) v = 0.5f * v * (1.f + erff(v * 0.70710678118654752f));
            if (RES)  v += res[(size_t)r * Nd + c];
            C[(size_t)r * Nd + c] = v;
        }
    }
}

// ---------------- causal attention scores + softmax ----------------
// grid: (S_, B_*H_), block 128.  attn[z, i, j] = softmax_j<=i (q_i . k_j / 8)
__global__ void attn_scores_kernel(const float* __restrict__ q,
                                   const float* __restrict__ k,
                                   float* __restrict__ attn)
{
    int i = blockIdx.x;
    int z = blockIdx.y;
    int b = z / H_, h = z % H_;
    int tid = threadIdx.x;

    __shared__ float qs[D_];
    __shared__ float red[128];

    const float* qrow = q + ((size_t)(b * S_ + i) * E_ + h * D_);
    if (tid < D_) qs[tid] = qrow[tid];
    __syncthreads();

    float sc[8];
    float lmax = -1e30f;
    #pragma unroll
    for (int it = 0; it < 8; ++it) {
        int j = tid + it * 128;
        float dot = -1e30f;
        if (j <= i) {
            const float4* kr = (const float4*)(k + ((size_t)(b * S_ + j) * E_ + h * D_));
            const float4* q4 = (const float4*)qs;
            float acc = 0.f;
            #pragma unroll
            for (int d = 0; d < D_ / 4; ++d) {
                float4 kv = kr[d], qv = q4[d];
                acc += kv.x * qv.x + kv.y * qv.y + kv.z * qv.z + kv.w * qv.w;
            }
            dot = acc * 0.125f;   // D^-0.5, D=64
        }
        sc[it] = dot;
        lmax = fmaxf(lmax, dot);
    }

    red[tid] = lmax; __syncthreads();
    for (int o = 64; o > 0; o >>= 1) { if (tid < o) red[tid] = fmaxf(red[tid], red[tid + o]); __syncthreads(); }
    float m = red[0]; __syncthreads();

    float lsum = 0.f;
    #pragma unroll
    for (int it = 0; it < 8; ++it) {
        int j = tid + it * 128;
        if (j <= i) { sc[it] = expf(sc[it] - m); lsum += sc[it]; }
    }
    red[tid] = lsum; __syncthreads();
    for (int o = 64; o > 0; o >>= 1) { if (tid < o) red[tid] += red[tid + o]; __syncthreads(); }
    float inv = 1.f / red[0];

    float* arow = attn + ((size_t)z * S_ + i) * S_;
    #pragma unroll
    for (int it = 0; it < 8; ++it) {
        int j = tid + it * 128;
        arow[j] = (j <= i) ? sc[it] * inv : 0.f;
    }
}

// ---------------- batched A·V: o[b,:,h*64:...] = attn[z] @ v_head ----------------
// grid: (1, S_/64, B_*H_), block 256.
__global__ void __launch_bounds__(256)
av_kernel(const float* __restrict__ attn, const float* __restrict__ v,
          float* __restrict__ o)
{
    const int BM = 64, BN = 64, BK = 16;
    int z = blockIdx.z;
    int b = z / H_, h = z % H_;
    const float* Az = attn + (size_t)z * S_ * S_;          // [S,S], lda=S
    const float* Bz = v + (size_t)b * S_ * E_ + h * D_;    // [S,64], ldb=E
    float*       Cz = o + (size_t)b * S_ * E_ + h * D_;    // [S,64], ldc=E

    __shared__ float As[BK][BM];
    __shared__ float Bs[BK][BN];

    int tid  = threadIdx.x;
    int row0 = blockIdx.y * BM;
    int tx = tid & 15, ty = tid >> 4;

    int arow = tid >> 2;
    int acol = (tid & 3) * 4;
    int brow = tid >> 4;
    int bcol = (tid & 15) * 4;

    float acc[4][4] = {};

    for (int k0 = 0; k0 < S_; k0 += BK) {
        float4 av = *(const float4*)(Az + (size_t)(row0 + arow) * S_ + k0 + acol);
        As[acol + 0][arow] = av.x;
        As[acol + 1][arow] = av.y;
        As[acol + 2][arow] = av.z;
        As[acol + 3][arow] = av.w;
        float4 bv = *(const float4*)(Bz + (size_t)(k0 + brow) * E_ + bcol);
        *(float4*)&Bs[brow][bcol] = bv;
        __syncthreads();

        #pragma unroll
        for (int kk = 0; kk < BK; ++kk) {
            float ar[4], br[4];
            #pragma unroll
            for (int i = 0; i < 4; ++i) ar[i] = As[kk][ty * 4 + i];
            #pragma unroll
            for (int j = 0; j < 4; ++j) br[j] = Bs[kk][tx * 4 + j];
            #pragma unroll
            for (int i = 0; i < 4; ++i)
                #pragma unroll
                for (int j = 0; j < 4; ++j)
                    acc[i][j] += ar[i] * br[j];
        }
        __syncthreads();
    }

    #pragma unroll
    for (int i = 0; i < 4; ++i) {
        int r = row0 + ty * 4 + i;
        #pragma unroll
        for (int j = 0; j < 4; ++j) {
            int c = tx * 4 + j;
            Cz[(size_t)r * E_ + c] = acc[i][j];
        }
    }
}

// ---------------- host launcher ----------------
extern "C" void kernel_launch(void* const* d_in, const int* in_sizes, int n_in,
                              void* d_out, int out_size)
{
    const int*   tokens  = (const int*)  d_in[0];
    const float* tok_emb = (const float*)d_in[1];
    const float* pos_emb = (const float*)d_in[2];
    const float* Wq = (const float*)d_in[3];
    const float* bq = (const float*)d_in[4];
    const float* Wk = (const float*)d_in[5];
    const float* bk = (const float*)d_in[6];
    const float* Wv = (const float*)d_in[7];
    const float* bv = (const float*)d_in[8];
    const float* Wo = (const float*)d_in[9];
    const float* bo = (const float*)d_in[10];
    const float* ln1_g = (const float*)d_in[11];
    const float* ln1_b = (const float*)d_in[12];
    const float* ln2_g = (const float*)d_in[13];
    const float* ln2_b = (const float*)d_in[14];
    const float* W1 = (const float*)d_in[15];
    const float* b1 = (const float*)d_in[16];
    const float* W2 = (const float*)d_in[17];
    const float* b2 = (const float*)d_in[18];
    const float* lnf_g = (const float*)d_in[19];
    const float* lnf_b = (const float*)d_in[20];
    const float* Wf = (const float*)d_in[21];
    const float* bf = (const float*)d_in[22];
    float* out = (float*)d_out;

    float *x, *h, *q, *k, *v, *o, *ff, *attn;
    cudaGetSymbolAddress((void**)&x,    g_x);
    cudaGetSymbolAddress((void**)&h,    g_h);
    cudaGetSymbolAddress((void**)&q,    g_q);
    cudaGetSymbolAddress((void**)&k,    g_k);
    cudaGetSymbolAddress((void**)&v,    g_v);
    cudaGetSymbolAddress((void**)&o,    g_o);
    cudaGetSymbolAddress((void**)&ff,   g_ff);
    cudaGetSymbolAddress((void**)&attn, g_attn);

    embed_kernel<<<M_, 192>>>(tokens, tok_emb, pos_emb, x);

    dim3 gProj(E_ / 64, M_ / 64);      // 12 x 32
    dim3 gFF1 (FF_ / 64, M_ / 64);     // 72 x 32
    dim3 gHead(V_ / 64, M_ / 64);      // 500 x 32
    dim3 gAttn(S_, B_ * H_);           // 1024 x 24
    dim3 gAV  (1, S_ / 64, B_ * H_);   // 1 x 16 x 24

    for (int l = 0; l < L_; ++l) {
        const float* wq = Wq + (size_t)l * E_ * E_;
        const float* wk = Wk + (size_t)l * E_ * E_;
        const float* wv = Wv + (size_t)l * E_ * E_;
        const float* wo = Wo + (size_t)l * E_ * E_;
        const float* w1 = W1 + (size_t)l * E_ * FF_;
        const float* w2 = W2 + (size_t)l * FF_ * E_;

        ln_kernel<<<M_, 256>>>(x, ln1_g + l * E_, ln1_b + l * E_, h);

        sgemm_kernel<true, false, false><<<gProj, 256>>>(h, wq, bq + l * E_, nullptr, q, M_, E_, E_);
        sgemm_kernel<true, false, false><<<gProj, 256>>>(h, wk, bk + l * E_, nullptr, k, M_, E_, E_);
        sgemm_kernel<true, false, false><<<gProj, 256>>>(h, wv, bv + l * E_, nullptr, v, M_, E_, E_);

        attn_scores_kernel<<<gAttn, 128>>>(q, k, attn);
        av_kernel<<<gAV, 256>>>(attn, v, o);

        // x = x + o @ Wo + bo
        sgemm_kernel<true, true, false><<<gProj, 256>>>(o, wo, bo + l * E_, x, x, M_, E_, E_);

        ln_kernel<<<M_, 256>>>(x, ln2_g + l * E_, ln2_b + l * E_, h);

        // ff = gelu(h @ W1 + b1)
        sgemm_kernel<true, false, true><<<gFF1, 256>>>(h, w1, b1 + l * FF_, nullptr, ff, M_, FF_, E_);
        // x = x + ff @ W2 + b2
        sgemm_kernel<true, true, false><<<gProj, 256>>>(ff, w2, b2 + l * E_, x, x, M_, E_, FF_);
    }

    ln_kernel<<<M_, 256>>>(x, lnf_g, lnf_b, h);
    sgemm_kernel<true, false, false><<<gHead, 256>>>(h, Wf, bf, nullptr, out, M_, V_, E_);
}

// round 5
// speedup vs baseline: 1.4218x; 1.4218x over previous
#include <cuda_runtime.h>
#include <cuda_bf16.h>
#include <math.h>
#include <stdint.h>

// Problem dims (compile-time)
#define E_  768
#define H_  12
#define D_  64
#define L_  4
#define S_  1024
#define B_  2
#define V_  32000
#define FF_ 4608
#define M_  (B_ * S_)   // 2048 rows

// ---------------- fp32 scratch ----------------
__device__ float g_x  [M_ * E_];
__device__ float g_h  [M_ * E_];
__device__ float g_q  [M_ * E_];
__device__ float g_k  [M_ * E_];
__device__ float g_v  [M_ * E_];
__device__ float g_o  [M_ * E_];
__device__ float g_ff [M_ * FF_];
__device__ float g_attn[(size_t)B_ * H_ * S_ * S_];   // ~100 MB

// ---------------- bf16 split-3 scratch ----------------
// Weights: W'[3K, N] = [Wh; Wl; Wh]
__device__ __nv_bfloat16 g_w3_qkvo[(size_t)L_ * 4 * 3 * E_ * E_];     // 28.3M
__device__ __nv_bfloat16 g_w3_w1  [(size_t)L_ * 3 * E_ * FF_];        // 42.5M
__device__ __nv_bfloat16 g_w3_w2  [(size_t)L_ * 3 * FF_ * E_];        // 42.5M
__device__ __nv_bfloat16 g_w3_wf  [(size_t)3 * E_ * V_];              // 73.7M
// Activations: A'[M, 3K] = [Ah | Ah | Al]
__device__ __nv_bfloat16 g_a3_s [(size_t)M_ * 3 * E_];                // 4.7M
__device__ __nv_bfloat16 g_a3_ff[(size_t)M_ * 3 * FF_];               // 28.3M

// ---------------- embedding ----------------
__global__ void embed_kernel(const int* __restrict__ tokens,
                             const float* __restrict__ tok_emb,
                             const float* __restrict__ pos_emb,
                             float* __restrict__ x)
{
    int row = blockIdx.x;
    int s   = row % S_;
    int t   = tokens[row];
    const float4* te = (const float4*)(tok_emb + (size_t)t * E_);
    const float4* pe = (const float4*)(pos_emb + (size_t)s * E_);
    float4*       xo = (float4*)(x + (size_t)row * E_);
    for (int i = threadIdx.x; i < E_ / 4; i += blockDim.x) {
        float4 a = te[i], b = pe[i];
        xo[i] = make_float4(a.x + b.x, a.y + b.y, a.z + b.z, a.w + b.w);
    }
}

// ---------------- layernorm ----------------
__global__ void ln_kernel(const float* __restrict__ x,
                          const float* __restrict__ g,
                          const float* __restrict__ b,
                          float* __restrict__ out)
{
    int row = blockIdx.x;
    const float* xr = x + (size_t)row * E_;
    __shared__ float red[256];
    int tid = threadIdx.x;

    float s = 0.f;
    for (int i = tid; i < E_; i += 256) s += xr[i];
    red[tid] = s; __syncthreads();
    for (int o = 128; o > 0; o >>= 1) { if (tid < o) red[tid] += red[tid + o]; __syncthreads(); }
    float mean = red[0] * (1.f / E_);
    __syncthreads();

    float sq = 0.f;
    for (int i = tid; i < E_; i += 256) { float d = xr[i] - mean; sq += d * d; }
    red[tid] = sq; __syncthreads();
    for (int o = 128; o > 0; o >>= 1) { if (tid < o) red[tid] += red[tid + o]; __syncthreads(); }
    float inv = rsqrtf(red[0] * (1.f / E_) + 1e-5f);

    float* orow = out + (size_t)row * E_;
    for (int i = tid; i < E_; i += 256)
        orow[i] = (xr[i] - mean) * inv * g[i] + b[i];
}

// ---------------- split-3 converters ----------------
// W[K,N] fp32 -> W3[3K,N] bf16 = [Wh; Wl; Wh]
__global__ void split3_B_kernel(const float* __restrict__ W,
                                __nv_bfloat16* __restrict__ W3, int K, int N)
{
    size_t total = (size_t)K * N;
    size_t KN = (size_t)K * N;
    for (size_t idx = (size_t)blockIdx.x * blockDim.x + threadIdx.x;
         idx < total; idx += (size_t)gridDim.x * blockDim.x) {
        float w = W[idx];
        __nv_bfloat16 h = __float2bfloat16(w);
        __nv_bfloat16 l = __float2bfloat16(w - __bfloat162float(h));
        W3[idx]          = h;
        W3[idx + KN]     = l;
        W3[idx + 2 * KN] = h;
    }
}

// A[M,K] fp32 -> A3[M,3K] bf16 = [Ah | Ah | Al]
__global__ void split3_A_kernel(const float* __restrict__ A,
                                __nv_bfloat16* __restrict__ A3, int M, int K)
{
    size_t total = (size_t)M * K;
    for (size_t idx = (size_t)blockIdx.x * blockDim.x + threadIdx.x;
         idx < total; idx += (size_t)gridDim.x * blockDim.x) {
        size_t m = idx / K, k = idx - m * K;
        float a = A[idx];
        __nv_bfloat16 h = __float2bfloat16(a);
        __nv_bfloat16 l = __float2bfloat16(a - __bfloat162float(h));
        __nv_bfloat16* row = A3 + m * (size_t)(3 * K);
        row[k]         = h;
        row[k + K]     = h;
        row[k + 2 * K] = l;
    }
}

// ---------------- PTX helpers ----------------
__device__ __forceinline__ void cp_async16(uint32_t s, const void* g) {
    asm volatile("cp.async.cg.shared.global [%0], [%1], 16;" :: "r"(s), "l"(g));
}
__device__ __forceinline__ void cp_commit() {
    asm volatile("cp.async.commit_group;");
}
template<int N>
__device__ __forceinline__ void cp_wait() {
    asm volatile("cp.async.wait_group %0;" :: "n"(N));
}
__device__ __forceinline__ void ldm_x4(uint32_t* r, uint32_t addr) {
    asm volatile("ldmatrix.sync.aligned.m8n8.x4.shared.b16 {%0,%1,%2,%3}, [%4];"
                 : "=r"(r[0]), "=r"(r[1]), "=r"(r[2]), "=r"(r[3]) : "r"(addr));
}
__device__ __forceinline__ void ldm_x4_trans(uint32_t* r, uint32_t addr) {
    asm volatile("ldmatrix.sync.aligned.m8n8.x4.trans.shared.b16 {%0,%1,%2,%3}, [%4];"
                 : "=r"(r[0]), "=r"(r[1]), "=r"(r[2]), "=r"(r[3]) : "r"(addr));
}
__device__ __forceinline__ void mma_bf16(float* d, const uint32_t* a, const uint32_t* b) {
    asm volatile(
        "mma.sync.aligned.m16n8k16.row.col.f32.bf16.bf16.f32 "
        "{%0,%1,%2,%3}, {%4,%5,%6,%7}, {%8,%9}, {%0,%1,%2,%3};"
        : "+f"(d[0]), "+f"(d[1]), "+f"(d[2]), "+f"(d[3])
        : "r"(a[0]), "r"(a[1]), "r"(a[2]), "r"(a[3]), "r"(b[0]), "r"(b[1]));
}

// ---------------- bf16 tensor-core GEMM ----------------
// C[M,N] = A[M,K3] @ B[K3,N]  (bf16 in, fp32 accum/out), fused epilogue.
// BM=128, BN=128, BK=32, 256 threads (8 warps, 4m x 2n, warp tile 32x64).
// Requires M%128==0, N%128==0, K3%32==0.
template<bool BIAS, bool RES, bool GELU>
__global__ void __launch_bounds__(256)
bgemm_kernel(const __nv_bfloat16* __restrict__ A, const __nv_bfloat16* __restrict__ Bm,
             const float* __restrict__ bias, const float* __restrict__ res,
             float* __restrict__ C, int Md, int Nd, int K3)
{
    const int LDA = 40;    // padded A smem row (bf16 elems): 80B -> conflict-free ldmatrix
    const int LDB = 136;   // padded B smem row: 272B -> conflict-free ldmatrix
    __shared__ __nv_bfloat16 As[2][128 * LDA];
    __shared__ __nv_bfloat16 Bs[2][32 * LDB];

    int tid  = threadIdx.x;
    int lane = tid & 31, wid = tid >> 5;
    int wm = wid & 3, wn = wid >> 2;
    int row0 = blockIdx.y * 128, col0 = blockIdx.x * 128;

    uint32_t asb[2], bsb[2];
    asb[0] = (uint32_t)__cvta_generic_to_shared(&As[0][0]);
    asb[1] = (uint32_t)__cvta_generic_to_shared(&As[1][0]);
    bsb[0] = (uint32_t)__cvta_generic_to_shared(&Bs[0][0]);
    bsb[1] = (uint32_t)__cvta_generic_to_shared(&Bs[1][0]);

    float acc[2][8][4];
    #pragma unroll
    for (int i = 0; i < 2; ++i)
        #pragma unroll
        for (int j = 0; j < 8; ++j)
            #pragma unroll
            for (int t = 0; t < 4; ++t) acc[i][j][t] = 0.f;

    const int KT = K3 / 32;

    auto load_tile = [&](int buf, int kt) {
        int k0 = kt * 32;
        #pragma unroll
        for (int i = 0; i < 2; ++i) {          // A: 512 16B-chunks
            int chunk = tid * 2 + i;
            int m = chunk >> 2, c = chunk & 3; // 4 chunks (32 elems) per row
            const void* g = A + (size_t)(row0 + m) * K3 + k0 + c * 8;
            cp_async16(asb[buf] + (uint32_t)(m * LDA + c * 8) * 2, g);
        }
        #pragma unroll
        for (int i = 0; i < 2; ++i) {          // B: 512 16B-chunks
            int chunk = tid * 2 + i;
            int k = chunk >> 4, c = chunk & 15; // 16 chunks (128 elems) per row
            const void* g = Bm + (size_t)(k0 + k) * Nd + col0 + c * 8;
            cp_async16(bsb[buf] + (uint32_t)(k * LDB + c * 8) * 2, g);
        }
        cp_commit();
    };

    load_tile(0, 0);

    for (int kt = 0; kt < KT; ++kt) {
        int buf = kt & 1;
        if (kt + 1 < KT) { load_tile(buf ^ 1, kt + 1); cp_wait<1>(); }
        else             { cp_wait<0>(); }
        __syncthreads();

        #pragma unroll
        for (int kk = 0; kk < 2; ++kk) {       // two k16 chunks
            uint32_t af[2][4];
            #pragma unroll
            for (int mi = 0; mi < 2; ++mi) {
                int m  = wm * 32 + mi * 16 + (lane & 15);
                int kc = kk * 16 + (lane >> 4) * 8;
                ldm_x4(af[mi], asb[buf] + (uint32_t)(m * LDA + kc) * 2);
            }
            uint32_t bf[8][2];
            #pragma unroll
            for (int ni4 = 0; ni4 < 4; ++ni4) { // each covers n16 -> 2 frags
                int g    = lane >> 3;
                int krow = kk * 16 + (g & 1) * 8 + (lane & 7);
                int ncol = wn * 64 + ni4 * 16 + (g >> 1) * 8;
                uint32_t r[4];
                ldm_x4_trans(r, bsb[buf] + (uint32_t)(krow * LDB + ncol) * 2);
                bf[2 * ni4][0] = r[0]; bf[2 * ni4][1] = r[1];
                bf[2 * ni4 + 1][0] = r[2]; bf[2 * ni4 + 1][1] = r[3];
            }
            #pragma unroll
            for (int mi = 0; mi < 2; ++mi)
                #pragma unroll
                for (int ni = 0; ni < 8; ++ni)
                    mma_bf16(acc[mi][ni], af[mi], bf[ni]);
        }
        __syncthreads();
    }

    // epilogue
    #pragma unroll
    for (int mi = 0; mi < 2; ++mi) {
        int r = row0 + wm * 32 + mi * 16 + (lane >> 2);
        #pragma unroll
        for (int ni = 0; ni < 8; ++ni) {
            int c = col0 + wn * 64 + ni * 8 + (lane & 3) * 2;
            float b0 = 0.f, b1 = 0.f;
            if (BIAS) { b0 = bias[c]; b1 = bias[c + 1]; }
            #pragma unroll
            for (int half = 0; half < 2; ++half) {
                int rr = r + half * 8;
                float v0 = acc[mi][ni][half * 2 + 0] + b0;
                float v1 = acc[mi][ni][half * 2 + 1] + b1;
                if (GELU) {
                    v0 = 0.5f * v0 * (1.f + erff(v0 * 0.70710678118654752f));
                    v1 = 0.5f * v1 * (1.f + erff(v1 * 0.70710678118654752f));
                }
                if (RES) {
                    const float2 rv = *(const float2*)(res + (size_t)rr * Nd + c);
                    v0 += rv.x; v1 += rv.y;
                }
                *(float2*)(C + (size_t)rr * Nd + c) = make_float2(v0, v1);
            }
        }
    }
}

// ---------------- causal attention scores + softmax (fp32) ----------------
__global__ void attn_scores_kernel(const float* __restrict__ q,
                                   const float* __restrict__ k,
                                   float* __restrict__ attn)
{
    int i = blockIdx.x;
    int z = blockIdx.y;
    int b = z / H_, h = z % H_;
    int tid = threadIdx.x;

    __shared__ float qs[D_];
    __shared__ float red[128];

    const float* qrow = q + ((size_t)(b * S_ + i) * E_ + h * D_);
    if (tid < D_) qs[tid] = qrow[tid];
    __syncthreads();

    float sc[8];
    float lmax = -1e30f;
    #pragma unroll
    for (int it = 0; it < 8; ++it) {
        int j = tid + it * 128;
        float dot = -1e30f;
        if (j <= i) {
            const float4* kr = (const float4*)(k + ((size_t)(b * S_ + j) * E_ + h * D_));
            const float4* q4 = (const float4*)qs;
            float a = 0.f;
            #pragma unroll
            for (int d = 0; d < D_ / 4; ++d) {
                float4 kv = kr[d], qv = q4[d];
                a += kv.x * qv.x + kv.y * qv.y + kv.z * qv.z + kv.w * qv.w;
            }
            dot = a * 0.125f;
        }
        sc[it] = dot;
        lmax = fmaxf(lmax, dot);
    }

    red[tid] = lmax; __syncthreads();
    for (int o = 64; o > 0; o >>= 1) { if (tid < o) red[tid] = fmaxf(red[tid], red[tid + o]); __syncthreads(); }
    float m = red[0]; __syncthreads();

    float lsum = 0.f;
    #pragma unroll
    for (int it = 0; it < 8; ++it) {
        int j = tid + it * 128;
        if (j <= i) { sc[it] = expf(sc[it] - m); lsum += sc[it]; }
    }
    red[tid] = lsum; __syncthreads();
    for (int o = 64; o > 0; o >>= 1) { if (tid < o) red[tid] += red[tid + o]; __syncthreads(); }
    float inv = 1.f / red[0];

    float* arow = attn + ((size_t)z * S_ + i) * S_;
    #pragma unroll
    for (int it = 0; it < 8; ++it) {
        int j = tid + it * 128;
        arow[j] = (j <= i) ? sc[it] * inv : 0.f;
    }
}

// ---------------- batched A*V (fp32) ----------------
__global__ void __launch_bounds__(256)
av_kernel(const float* __restrict__ attn, const float* __restrict__ v,
          float* __restrict__ o)
{
    const int BM = 64, BK = 16;
    int z = blockIdx.z;
    int b = z / H_, h = z % H_;
    const float* Az = attn + (size_t)z * S_ * S_;
    const float* Bz = v + (size_t)b * S_ * E_ + h * D_;
    float*       Cz = o + (size_t)b * S_ * E_ + h * D_;

    __shared__ float As[BK][BM];
    __shared__ float Bs[BK][64];

    int tid  = threadIdx.x;
    int row0 = blockIdx.y * BM;
    int tx = tid & 15, ty = tid >> 4;

    int arow = tid >> 2;
    int acol = (tid & 3) * 4;
    int brow = tid >> 4;
    int bcol = (tid & 15) * 4;

    float acc[4][4] = {};

    for (int k0 = 0; k0 < S_; k0 += BK) {
        float4 av = *(const float4*)(Az + (size_t)(row0 + arow) * S_ + k0 + acol);
        As[acol + 0][arow] = av.x;
        As[acol + 1][arow] = av.y;
        As[acol + 2][arow] = av.z;
        As[acol + 3][arow] = av.w;
        float4 bv = *(const float4*)(Bz + (size_t)(k0 + brow) * E_ + bcol);
        *(float4*)&Bs[brow][bcol] = bv;
        __syncthreads();

        #pragma unroll
        for (int kk = 0; kk < BK; ++kk) {
            float ar[4], br[4];
            #pragma unroll
            for (int i = 0; i < 4; ++i) ar[i] = As[kk][ty * 4 + i];
            #pragma unroll
            for (int j = 0; j < 4; ++j) br[j] = Bs[kk][tx * 4 + j];
            #pragma unroll
            for (int i = 0; i < 4; ++i)
                #pragma unroll
                for (int j = 0; j < 4; ++j)
                    acc[i][j] += ar[i] * br[j];
        }
        __syncthreads();
    }

    #pragma unroll
    for (int i = 0; i < 4; ++i) {
        int r = row0 + ty * 4 + i;
        #pragma unroll
        for (int j = 0; j < 4; ++j)
            Cz[(size_t)r * E_ + tx * 4 + j] = acc[i][j];
    }
}

// ---------------- host launcher ----------------
extern "C" void kernel_launch(void* const* d_in, const int* in_sizes, int n_in,
                              void* d_out, int out_size)
{
    const int*   tokens  = (const int*)  d_in[0];
    const float* tok_emb = (const float*)d_in[1];
    const float* pos_emb = (const float*)d_in[2];
    const float* Wq = (const float*)d_in[3];
    const float* bq = (const float*)d_in[4];
    const float* Wk = (const float*)d_in[5];
    const float* bk = (const float*)d_in[6];
    const float* Wv = (const float*)d_in[7];
    const float* bv = (const float*)d_in[8];
    const float* Wo = (const float*)d_in[9];
    const float* bo = (const float*)d_in[10];
    const float* ln1_g = (const float*)d_in[11];
    const float* ln1_b = (const float*)d_in[12];
    const float* ln2_g = (const float*)d_in[13];
    const float* ln2_b = (const float*)d_in[14];
    const float* W1 = (const float*)d_in[15];
    const float* b1 = (const float*)d_in[16];
    const float* W2 = (const float*)d_in[17];
    const float* b2 = (const float*)d_in[18];
    const float* lnf_g = (const float*)d_in[19];
    const float* lnf_b = (const float*)d_in[20];
    const float* Wf = (const float*)d_in[21];
    const float* bf = (const float*)d_in[22];
    float* out = (float*)d_out;

    float *x, *h, *q, *k, *v, *o, *ff, *attn;
    cudaGetSymbolAddress((void**)&x,    g_x);
    cudaGetSymbolAddress((void**)&h,    g_h);
    cudaGetSymbolAddress((void**)&q,    g_q);
    cudaGetSymbolAddress((void**)&k,    g_k);
    cudaGetSymbolAddress((void**)&v,    g_v);
    cudaGetSymbolAddress((void**)&o,    g_o);
    cudaGetSymbolAddress((void**)&ff,   g_ff);
    cudaGetSymbolAddress((void**)&attn, g_attn);

    __nv_bfloat16 *w3qkvo, *w3w1, *w3w2, *w3wf, *a3s, *a3ff;
    cudaGetSymbolAddress((void**)&w3qkvo, g_w3_qkvo);
    cudaGetSymbolAddress((void**)&w3w1,   g_w3_w1);
    cudaGetSymbolAddress((void**)&w3w2,   g_w3_w2);
    cudaGetSymbolAddress((void**)&w3wf,   g_w3_wf);
    cudaGetSymbolAddress((void**)&a3s,    g_a3_s);
    cudaGetSymbolAddress((void**)&a3ff,   g_a3_ff);

    // ---- weight split (every launch; deterministic) ----
    const size_t EE = (size_t)E_ * E_;
    for (int l = 0; l < L_; ++l) {
        split3_B_kernel<<<1024, 256>>>(Wq + l * EE, w3qkvo + ((size_t)l * 4 + 0) * 3 * EE, E_, E_);
        split3_B_kernel<<<1024, 256>>>(Wk + l * EE, w3qkvo + ((size_t)l * 4 + 1) * 3 * EE, E_, E_);
        split3_B_kernel<<<1024, 256>>>(Wv + l * EE, w3qkvo + ((size_t)l * 4 + 2) * 3 * EE, E_, E_);
        split3_B_kernel<<<1024, 256>>>(Wo + l * EE, w3qkvo + ((size_t)l * 4 + 3) * 3 * EE, E_, E_);
        split3_B_kernel<<<2048, 256>>>(W1 + (size_t)l * E_ * FF_, w3w1 + (size_t)l * 3 * E_ * FF_, E_, FF_);
        split3_B_kernel<<<2048, 256>>>(W2 + (size_t)l * FF_ * E_, w3w2 + (size_t)l * 3 * FF_ * E_, FF_, E_);
    }
    split3_B_kernel<<<4096, 256>>>(Wf, w3wf, E_, V_);

    embed_kernel<<<M_, 192>>>(tokens, tok_emb, pos_emb, x);

    dim3 gProj(E_ / 128, M_ / 128);     // 6 x 16
    dim3 gFF1 (FF_ / 128, M_ / 128);    // 36 x 16
    dim3 gHead(V_ / 128, M_ / 128);     // 250 x 16
    dim3 gAttn(S_, B_ * H_);
    dim3 gAV  (1, S_ / 64, B_ * H_);

    for (int l = 0; l < L_; ++l) {
        const __nv_bfloat16* wq3 = w3qkvo + ((size_t)l * 4 + 0) * 3 * EE;
        const __nv_bfloat16* wk3 = w3qkvo + ((size_t)l * 4 + 1) * 3 * EE;
        const __nv_bfloat16* wv3 = w3qkvo + ((size_t)l * 4 + 2) * 3 * EE;
        const __nv_bfloat16* wo3 = w3qkvo + ((size_t)l * 4 + 3) * 3 * EE;
        const __nv_bfloat16* w13 = w3w1 + (size_t)l * 3 * E_ * FF_;
        const __nv_bfloat16* w23 = w3w2 + (size_t)l * 3 * FF_ * E_;

        ln_kernel<<<M_, 256>>>(x, ln1_g + l * E_, ln1_b + l * E_, h);
        split3_A_kernel<<<1024, 256>>>(h, a3s, M_, E_);

        bgemm_kernel<true, false, false><<<gProj, 256>>>(a3s, wq3, bq + l * E_, nullptr, q, M_, E_, 3 * E_);
        bgemm_kernel<true, false, false><<<gProj, 256>>>(a3s, wk3, bk + l * E_, nullptr, k, M_, E_, 3 * E_);
        bgemm_kernel<true, false, false><<<gProj, 256>>>(a3s, wv3, bv + l * E_, nullptr, v, M_, E_, 3 * E_);

        attn_scores_kernel<<<gAttn, 128>>>(q, k, attn);
        av_kernel<<<gAV, 256>>>(attn, v, o);

        split3_A_kernel<<<1024, 256>>>(o, a3s, M_, E_);
        bgemm_kernel<true, true, false><<<gProj, 256>>>(a3s, wo3, bo + l * E_, x, x, M_, E_, 3 * E_);

        ln_kernel<<<M_, 256>>>(x, ln2_g + l * E_, ln2_b + l * E_, h);
        split3_A_kernel<<<1024, 256>>>(h, a3s, M_, E_);
        bgemm_kernel<true, false, true><<<gFF1, 256>>>(a3s, w13, b1 + l * FF_, nullptr, ff, M_, FF_, 3 * E_);

        split3_A_kernel<<<2048, 256>>>(ff, a3ff, M_, FF_);
        bgemm_kernel<true, true, false><<<gProj, 256>>>(a3ff, w23, b2 + l * E_, x, x, M_, E_, 3 * FF_);
    }

    ln_kernel<<<M_, 256>>>(x, lnf_g, lnf_b, h);
    split3_A_kernel<<<1024, 256>>>(h, a3s, M_, E_);
    bgemm_kernel<true, false, false><<<gHead, 256>>>(a3s, w3wf, bf, nullptr, out, M_, V_, 3 * E_);
}

// round 9
// speedup vs baseline: 2.7396x; 1.9269x over previous
#include <cuda_runtime.h>
#include <cuda_bf16.h>
#include <math.h>
#include <stdint.h>

// Problem dims (compile-time)
#define E_  768
#define H_  12
#define D_  64
#define L_  4
#define S_  1024
#define B_  2
#define V_  32000
#define FF_ 4608
#define M_  (B_ * S_)   // 2048 rows
#define QKVN 2304       // 3*E

// ---------------- scratch ----------------
__device__ float g_x[M_ * E_];                       // residual stream (fp32)
__device__ float g_bqkv[L_ * QKVN];                  // concatenated qkv bias
__device__ __nv_bfloat16 g_qkvh[(size_t)M_ * QKVN];  // qkv hi plane
__device__ __nv_bfloat16 g_qkvl[(size_t)M_ * QKVN];  // qkv lo plane
// activation split planes
__device__ __nv_bfloat16 g_ahE[(size_t)M_ * E_];
__device__ __nv_bfloat16 g_alE[(size_t)M_ * E_];
__device__ __nv_bfloat16 g_ahF[(size_t)M_ * FF_];
__device__ __nv_bfloat16 g_alF[(size_t)M_ * FF_];
// weight split planes
__device__ __nv_bfloat16 g_wqkv_h[(size_t)L_ * E_ * QKVN];
__device__ __nv_bfloat16 g_wqkv_l[(size_t)L_ * E_ * QKVN];
__device__ __nv_bfloat16 g_wo_h[(size_t)L_ * E_ * E_];
__device__ __nv_bfloat16 g_wo_l[(size_t)L_ * E_ * E_];
__device__ __nv_bfloat16 g_w1_h[(size_t)L_ * E_ * FF_];
__device__ __nv_bfloat16 g_w1_l[(size_t)L_ * E_ * FF_];
__device__ __nv_bfloat16 g_w2_h[(size_t)L_ * FF_ * E_];
__device__ __nv_bfloat16 g_w2_l[(size_t)L_ * FF_ * E_];
__device__ __nv_bfloat16 g_wf_h[(size_t)E_ * V_];
__device__ __nv_bfloat16 g_wf_l[(size_t)E_ * V_];

// ---------------- small helpers ----------------
__device__ __forceinline__ uint32_t pack_bf2(float a, float b) {
    __nv_bfloat162 t = __floats2bfloat162_rn(a, b);
    return *reinterpret_cast<uint32_t*>(&t);
}
__device__ __forceinline__ void split_write2(float v0, float v1,
                                             __nv_bfloat16* ph, __nv_bfloat16* pl) {
    __nv_bfloat16 h0 = __float2bfloat16(v0), h1 = __float2bfloat16(v1);
    __nv_bfloat162 hh; hh.x = h0; hh.y = h1;
    *(__nv_bfloat162*)ph = hh;
    __nv_bfloat162 ll;
    ll.x = __float2bfloat16(v0 - __bfloat162float(h0));
    ll.y = __float2bfloat16(v1 - __bfloat162float(h1));
    *(__nv_bfloat162*)pl = ll;
}
// split one float pair into hi/lo packed regs
__device__ __forceinline__ void split_pack2(float a, float b, uint32_t& hi, uint32_t& lo) {
    __nv_bfloat16 ha = __float2bfloat16(a), hb = __float2bfloat16(b);
    __nv_bfloat162 hh; hh.x = ha; hh.y = hb;
    hi = *reinterpret_cast<uint32_t*>(&hh);
    lo = pack_bf2(a - __bfloat162float(ha), b - __bfloat162float(hb));
}

// ---------------- embedding ----------------
__global__ void embed_kernel(const int* __restrict__ tokens,
                             const float* __restrict__ tok_emb,
                             const float* __restrict__ pos_emb,
                             float* __restrict__ x)
{
    int row = blockIdx.x;
    int s   = row % S_;
    int t   = tokens[row];
    const float4* te = (const float4*)(tok_emb + (size_t)t * E_);
    const float4* pe = (const float4*)(pos_emb + (size_t)s * E_);
    float4*       xo = (float4*)(x + (size_t)row * E_);
    for (int i = threadIdx.x; i < E_ / 4; i += blockDim.x) {
        float4 a = te[i], b = pe[i];
        xo[i] = make_float4(a.x + b.x, a.y + b.y, a.z + b.z, a.w + b.w);
    }
}

// ---------------- layernorm -> split planes ----------------
__global__ void ln_split_kernel(const float* __restrict__ x,
                                const float* __restrict__ g,
                                const float* __restrict__ b,
                                __nv_bfloat16* __restrict__ oh,
                                __nv_bfloat16* __restrict__ ol)
{
    int row = blockIdx.x;
    const float* xr = x + (size_t)row * E_;
    __shared__ float red[256];
    int tid = threadIdx.x;

    float s = 0.f;
    for (int i = tid; i < E_; i += 256) s += xr[i];
    red[tid] = s; __syncthreads();
    for (int o = 128; o > 0; o >>= 1) { if (tid < o) red[tid] += red[tid + o]; __syncthreads(); }
    float mean = red[0] * (1.f / E_);
    __syncthreads();

    float sq = 0.f;
    for (int i = tid; i < E_; i += 256) { float d = xr[i] - mean; sq += d * d; }
    red[tid] = sq; __syncthreads();
    for (int o = 128; o > 0; o >>= 1) { if (tid < o) red[tid] += red[tid + o]; __syncthreads(); }
    float inv = rsqrtf(red[0] * (1.f / E_) + 1e-5f);

    __nv_bfloat16* ohr = oh + (size_t)row * E_;
    __nv_bfloat16* olr = ol + (size_t)row * E_;
    for (int i = tid; i < E_; i += 256) {
        float v = (xr[i] - mean) * inv * g[i] + b[i];
        __nv_bfloat16 hh = __float2bfloat16(v);
        ohr[i] = hh;
        olr[i] = __float2bfloat16(v - __bfloat162float(hh));
    }
}

// ---------------- weight split: W[K,N] fp32 -> Wh, Wl bf16 (col offset into wider dst) ----------------
__global__ void split2_kernel(const float4* __restrict__ W,
                              uint2* __restrict__ Wh, uint2* __restrict__ Wl,
                              int K, int N4, int ld4, int col04)
{
    int total = K * N4;
    for (int idx = blockIdx.x * blockDim.x + threadIdx.x; idx < total;
         idx += gridDim.x * blockDim.x) {
        int k = idx / N4, n = idx - k * N4;
        float4 w = W[idx];
        uint2 hv, lv;
        split_pack2(w.x, w.y, hv.x, lv.x);
        split_pack2(w.z, w.w, hv.y, lv.y);
        size_t o = (size_t)k * ld4 + col04 + n;
        Wh[o] = hv; Wl[o] = lv;
    }
}

__global__ void concat_bias_kernel(const float* __restrict__ bq,
                                   const float* __restrict__ bk,
                                   const float* __restrict__ bv,
                                   float* __restrict__ bqkv)
{
    int t = blockIdx.x * blockDim.x + threadIdx.x;
    if (t >= L_ * QKVN) return;
    int l = t / QKVN, c = t - l * QKVN;
    float v;
    if (c < E_)           v = bq[l * E_ + c];
    else if (c < 2 * E_)  v = bk[l * E_ + c - E_];
    else                  v = bv[l * E_ + c - 2 * E_];
    bqkv[t] = v;
}

// ---------------- PTX helpers ----------------
__device__ __forceinline__ void cp_async16(uint32_t s, const void* g) {
    asm volatile("cp.async.cg.shared.global [%0], [%1], 16;" :: "r"(s), "l"(g));
}
__device__ __forceinline__ void cp_commit() {
    asm volatile("cp.async.commit_group;");
}
template<int N>
__device__ __forceinline__ void cp_wait() {
    asm volatile("cp.async.wait_group %0;" :: "n"(N));
}
__device__ __forceinline__ void ldm_x4(uint32_t* r, uint32_t addr) {
    asm volatile("ldmatrix.sync.aligned.m8n8.x4.shared.b16 {%0,%1,%2,%3}, [%4];"
                 : "=r"(r[0]), "=r"(r[1]), "=r"(r[2]), "=r"(r[3]) : "r"(addr));
}
__device__ __forceinline__ void ldm_x4_trans(uint32_t* r, uint32_t addr) {
    asm volatile("ldmatrix.sync.aligned.m8n8.x4.trans.shared.b16 {%0,%1,%2,%3}, [%4];"
                 : "=r"(r[0]), "=r"(r[1]), "=r"(r[2]), "=r"(r[3]) : "r"(addr));
}
__device__ __forceinline__ void mma_bf16(float* d, const uint32_t* a, const uint32_t* b) {
    asm volatile(
        "mma.sync.aligned.m16n8k16.row.col.f32.bf16.bf16.f32 "
        "{%0,%1,%2,%3}, {%4,%5,%6,%7}, {%8,%9}, {%0,%1,%2,%3};"
        : "+f"(d[0]), "+f"(d[1]), "+f"(d[2]), "+f"(d[3])
        : "r"(a[0]), "r"(a[1]), "r"(a[2]), "r"(a[3]), "r"(b[0]), "r"(b[1]));
}

// ---------------- split-plane bf16 tensor-core GEMM ----------------
// C[M,N] = Ah@Bh + Ah@Bl + Al@Bh  over per-plane K.
// blockIdx.x = M tile (fast dim -> B-stripe reuse in L2), blockIdx.y = N tile.
// OUT: 0 = fp32 C (bias/res), 1 = bf16 C (bias), 2 = split planes Co/Co2 (bias/gelu)
template<int OUT, bool BIAS, bool RES, bool GELU>
__global__ void __launch_bounds__(256)
bgemm2_kernel(const __nv_bfloat16* __restrict__ Ah, const __nv_bfloat16* __restrict__ Al,
              const __nv_bfloat16* __restrict__ Bh, const __nv_bfloat16* __restrict__ Bl,
              const float* __restrict__ bias, const float* __restrict__ res,
              float* __restrict__ Cf, __nv_bfloat16* __restrict__ Co,
              __nv_bfloat16* __restrict__ Co2, int Nd, int Kd)
{
    const int LDA = 40;
    const int LDB = 136;
    __shared__ __nv_bfloat16 As[2][128 * LDA];
    __shared__ __nv_bfloat16 Bs[2][32 * LDB];

    int tid  = threadIdx.x;
    int lane = tid & 31, wid = tid >> 5;
    int wm = wid & 3, wn = wid >> 2;
    int row0 = blockIdx.x * 128, col0 = blockIdx.y * 128;

    uint32_t asb[2], bsb[2];
    asb[0] = (uint32_t)__cvta_generic_to_shared(&As[0][0]);
    asb[1] = (uint32_t)__cvta_generic_to_shared(&As[1][0]);
    bsb[0] = (uint32_t)__cvta_generic_to_shared(&Bs[0][0]);
    bsb[1] = (uint32_t)__cvta_generic_to_shared(&Bs[1][0]);

    float acc[2][8][4];
    #pragma unroll
    for (int i = 0; i < 2; ++i)
        #pragma unroll
        for (int j = 0; j < 8; ++j)
            #pragma unroll
            for (int t = 0; t < 4; ++t) acc[i][j][t] = 0.f;

    const int KSEG = Kd / 32;
    const int KT   = 3 * KSEG;

    auto load_tile = [&](int buf, int kt) {
        int seg = (kt < KSEG) ? 0 : (kt < 2 * KSEG ? 1 : 2);
        const __nv_bfloat16* Ab = (seg == 2) ? Al : Ah;
        const __nv_bfloat16* Bb = (seg == 1) ? Bl : Bh;
        int k0 = (kt - seg * KSEG) * 32;
        #pragma unroll
        for (int i = 0; i < 2; ++i) {
            int chunk = tid * 2 + i;
            int m = chunk >> 2, c = chunk & 3;
            const void* g = Ab + (size_t)(row0 + m) * Kd + k0 + c * 8;
            cp_async16(asb[buf] + (uint32_t)(m * LDA + c * 8) * 2, g);
        }
        #pragma unroll
        for (int i = 0; i < 2; ++i) {
            int chunk = tid * 2 + i;
            int k = chunk >> 4, c = chunk & 15;
            const void* g = Bb + (size_t)(k0 + k) * Nd + col0 + c * 8;
            cp_async16(bsb[buf] + (uint32_t)(k * LDB + c * 8) * 2, g);
        }
        cp_commit();
    };

    load_tile(0, 0);

    for (int kt = 0; kt < KT; ++kt) {
        int buf = kt & 1;
        if (kt + 1 < KT) { load_tile(buf ^ 1, kt + 1); cp_wait<1>(); }
        else             { cp_wait<0>(); }
        __syncthreads();

        #pragma unroll
        for (int kk = 0; kk < 2; ++kk) {
            uint32_t af[2][4];
            #pragma unroll
            for (int mi = 0; mi < 2; ++mi) {
                int m  = wm * 32 + mi * 16 + (lane & 15);
                int kc = kk * 16 + (lane >> 4) * 8;
                ldm_x4(af[mi], asb[buf] + (uint32_t)(m * LDA + kc) * 2);
            }
            uint32_t bfrag[8][2];
            #pragma unroll
            for (int ni4 = 0; ni4 < 4; ++ni4) {
                int g    = lane >> 3;
                int krow = kk * 16 + (g & 1) * 8 + (lane & 7);
                int ncol = wn * 64 + ni4 * 16 + (g >> 1) * 8;
                uint32_t r[4];
                ldm_x4_trans(r, bsb[buf] + (uint32_t)(krow * LDB + ncol) * 2);
                bfrag[2 * ni4][0] = r[0]; bfrag[2 * ni4][1] = r[1];
                bfrag[2 * ni4 + 1][0] = r[2]; bfrag[2 * ni4 + 1][1] = r[3];
            }
            #pragma unroll
            for (int mi = 0; mi < 2; ++mi)
                #pragma unroll
                for (int ni = 0; ni < 8; ++ni)
                    mma_bf16(acc[mi][ni], af[mi], bfrag[ni]);
        }
        __syncthreads();
    }

    // epilogue
    #pragma unroll
    for (int mi = 0; mi < 2; ++mi) {
        int r = row0 + wm * 32 + mi * 16 + (lane >> 2);
        #pragma unroll
        for (int ni = 0; ni < 8; ++ni) {
            int c = col0 + wn * 64 + ni * 8 + (lane & 3) * 2;
            float b0 = 0.f, b1 = 0.f;
            if (BIAS) { b0 = bias[c]; b1 = bias[c + 1]; }
            #pragma unroll
            for (int half = 0; half < 2; ++half) {
                int rr = r + half * 8;
                float v0 = acc[mi][ni][half * 2 + 0] + b0;
                float v1 = acc[mi][ni][half * 2 + 1] + b1;
                if (GELU) {
                    v0 = 0.5f * v0 * (1.f + erff(v0 * 0.70710678118654752f));
                    v1 = 0.5f * v1 * (1.f + erff(v1 * 0.70710678118654752f));
                }
                if (RES) {
                    const float2 rv = *(const float2*)(res + (size_t)rr * Nd + c);
                    v0 += rv.x; v1 += rv.y;
                }
                if (OUT == 0) {
                    *(float2*)(Cf + (size_t)rr * Nd + c) = make_float2(v0, v1);
                } else if (OUT == 1) {
                    __nv_bfloat162 hv; hv.x = __float2bfloat16(v0); hv.y = __float2bfloat16(v1);
                    *(__nv_bfloat162*)(Co + (size_t)rr * Nd + c) = hv;
                } else {
                    split_write2(v0, v1, Co + (size_t)rr * Nd + c, Co2 + (size_t)rr * Nd + c);
                }
            }
        }
    }
}

// ---------------- flash attention (split-3 bf16 tensor core, online softmax) ----------------
// qkvh/qkvl: [M, 2304] bf16 split planes (q|k|v each 768 = 12 heads x 64).
// S = Qh Kh^T + Qh Kl^T + Ql Kh^T; O += Ph Vh + Ph Vl + Pl Vh.
// Writes o (fp32) split into (oh, ol) planes at [M, E], cols h*64..h*64+63.
#define LDQ 72
#define FA_TILE (64 * LDQ)
__global__ void __launch_bounds__(128)
flash_kernel(const __nv_bfloat16* __restrict__ qkvh,
             const __nv_bfloat16* __restrict__ qkvl,
             __nv_bfloat16* __restrict__ oh, __nv_bfloat16* __restrict__ ol)
{
    extern __shared__ __nv_bfloat16 smem[];
    __nv_bfloat16* Qh = smem;
    __nv_bfloat16* Ql = Qh + FA_TILE;
    __nv_bfloat16* Kh = Ql + FA_TILE;
    __nv_bfloat16* Kl = Kh + FA_TILE;
    __nv_bfloat16* Vh = Kl + FA_TILE;
    __nv_bfloat16* Vl = Vh + FA_TILE;

    int it = blockIdx.x;          // q tile
    int z  = blockIdx.y;          // b*H + h
    int b = z / H_, h = z % H_;
    int tid = threadIdx.x, lane = tid & 31, wm = tid >> 5;
    size_t rowbase = (size_t)b * S_;

    // load Q tiles (hi + lo)
    {
        size_t qoff = (rowbase + it * 64) * QKVN + h * D_;
        for (int cc = tid; cc < 512; cc += 128) {
            int r = cc >> 3, c = cc & 7;
            *(uint4*)&Qh[r * LDQ + c * 8] = *(const uint4*)(qkvh + qoff + (size_t)r * QKVN + c * 8);
            *(uint4*)&Ql[r * LDQ + c * 8] = *(const uint4*)(qkvl + qoff + (size_t)r * QKVN + c * 8);
        }
    }
    uint32_t qh_s = (uint32_t)__cvta_generic_to_shared(Qh);
    uint32_t ql_s = (uint32_t)__cvta_generic_to_shared(Ql);
    uint32_t kh_s = (uint32_t)__cvta_generic_to_shared(Kh);
    uint32_t kl_s = (uint32_t)__cvta_generic_to_shared(Kl);
    uint32_t vh_s = (uint32_t)__cvta_generic_to_shared(Vh);
    uint32_t vl_s = (uint32_t)__cvta_generic_to_shared(Vl);

    float oacc[8][4];
    #pragma unroll
    for (int j = 0; j < 8; ++j)
        #pragma unroll
        for (int t = 0; t < 4; ++t) oacc[j][t] = 0.f;
    float m_prev[2] = { -1e30f, -1e30f };
    float lsum[2]   = { 0.f, 0.f };

    for (int jt = 0; jt <= it; ++jt) {
        __syncthreads();
        size_t koff = (rowbase + jt * 64) * QKVN + E_ + h * D_;
        size_t voff = koff + E_;
        for (int cc = tid; cc < 512; cc += 128) {
            int r = cc >> 3, c = cc & 7;
            size_t gr = (size_t)r * QKVN + c * 8;
            int so = r * LDQ + c * 8;
            *(uint4*)&Kh[so] = *(const uint4*)(qkvh + koff + gr);
            *(uint4*)&Kl[so] = *(const uint4*)(qkvl + koff + gr);
            *(uint4*)&Vh[so] = *(const uint4*)(qkvh + voff + gr);
            *(uint4*)&Vl[so] = *(const uint4*)(qkvl + voff + gr);
        }
        __syncthreads();

        // S = Qh Kh + Qh Kl + Ql Kh
        float sacc[8][4];
        #pragma unroll
        for (int j = 0; j < 8; ++j)
            #pragma unroll
            for (int t = 0; t < 4; ++t) sacc[j][t] = 0.f;

        #pragma unroll
        for (int kc = 0; kc < 4; ++kc) {
            uint32_t a_off = (uint32_t)((wm * 16 + (lane & 15)) * LDQ + kc * 16 + (lane >> 4) * 8) * 2;
            uint32_t afh[4], afl[4];
            ldm_x4(afh, qh_s + a_off);
            ldm_x4(afl, ql_s + a_off);
            #pragma unroll
            for (int np = 0; np < 4; ++np) {
                int nrow = np * 16 + (lane & 7) + ((lane >> 4) << 3);
                int ncol = kc * 16 + ((lane >> 3) & 1) * 8;
                uint32_t b_off = (uint32_t)(nrow * LDQ + ncol) * 2;
                uint32_t brh[4], brl[4];
                ldm_x4(brh, kh_s + b_off);
                ldm_x4(brl, kl_s + b_off);
                mma_bf16(sacc[np * 2],     afh, brh);
                mma_bf16(sacc[np * 2],     afh, brl);
                mma_bf16(sacc[np * 2],     afl, brh);
                mma_bf16(sacc[np * 2 + 1], afh, brh + 2);
                mma_bf16(sacc[np * 2 + 1], afh, brl + 2);
                mma_bf16(sacc[np * 2 + 1], afl, brh + 2);
            }
        }

        // scale + causal mask + rowmax
        int rloc = wm * 16 + (lane >> 2);
        float mtile[2] = { -1e30f, -1e30f };
        bool diag = (jt == it);
        #pragma unroll
        for (int j = 0; j < 8; ++j) {
            int cg = jt * 64 + j * 8 + (lane & 3) * 2;
            #pragma unroll
            for (int rh = 0; rh < 2; ++rh) {
                int rg = it * 64 + rloc + rh * 8;
                float s0 = sacc[j][rh * 2]     * 0.125f;
                float s1 = sacc[j][rh * 2 + 1] * 0.125f;
                if (diag) {
                    if (cg     > rg) s0 = -1e30f;
                    if (cg + 1 > rg) s1 = -1e30f;
                }
                sacc[j][rh * 2]     = s0;
                sacc[j][rh * 2 + 1] = s1;
                mtile[rh] = fmaxf(mtile[rh], fmaxf(s0, s1));
            }
        }
        #pragma unroll
        for (int rh = 0; rh < 2; ++rh) {
            mtile[rh] = fmaxf(mtile[rh], __shfl_xor_sync(0xffffffff, mtile[rh], 1));
            mtile[rh] = fmaxf(mtile[rh], __shfl_xor_sync(0xffffffff, mtile[rh], 2));
        }
        float alpha[2];
        #pragma unroll
        for (int rh = 0; rh < 2; ++rh) {
            float mn = fmaxf(m_prev[rh], mtile[rh]);
            alpha[rh] = __expf(m_prev[rh] - mn);
            m_prev[rh] = mn;
        }
        // P = exp(S - m), rowsum
        float rsum[2] = { 0.f, 0.f };
        #pragma unroll
        for (int j = 0; j < 8; ++j)
            #pragma unroll
            for (int rh = 0; rh < 2; ++rh) {
                float p0 = __expf(sacc[j][rh * 2]     - m_prev[rh]);
                float p1 = __expf(sacc[j][rh * 2 + 1] - m_prev[rh]);
                sacc[j][rh * 2] = p0; sacc[j][rh * 2 + 1] = p1;
                rsum[rh] += p0 + p1;
            }
        #pragma unroll
        for (int rh = 0; rh < 2; ++rh) {
            rsum[rh] += __shfl_xor_sync(0xffffffff, rsum[rh], 1);
            rsum[rh] += __shfl_xor_sync(0xffffffff, rsum[rh], 2);
            lsum[rh] = lsum[rh] * alpha[rh] + rsum[rh];
        }
        // rescale O
        #pragma unroll
        for (int j = 0; j < 8; ++j)
            #pragma unroll
            for (int rh = 0; rh < 2; ++rh) {
                oacc[j][rh * 2]     *= alpha[rh];
                oacc[j][rh * 2 + 1] *= alpha[rh];
            }
        // O += Ph Vh + Ph Vl + Pl Vh   (P acc frags split + repacked as A frags)
        #pragma unroll
        for (int kc = 0; kc < 4; ++kc) {
            uint32_t pah[4], pal[4];
            split_pack2(sacc[2 * kc][0],     sacc[2 * kc][1],     pah[0], pal[0]);
            split_pack2(sacc[2 * kc][2],     sacc[2 * kc][3],     pah[1], pal[1]);
            split_pack2(sacc[2 * kc + 1][0], sacc[2 * kc + 1][1], pah[2], pal[2]);
            split_pack2(sacc[2 * kc + 1][2], sacc[2 * kc + 1][3], pah[3], pal[3]);
            #pragma unroll
            for (int np = 0; np < 4; ++np) {
                int g = lane >> 3;
                int krow = kc * 16 + (g & 1) * 8 + (lane & 7);
                int ncol = np * 16 + (g >> 1) * 8;
                uint32_t v_off = (uint32_t)(krow * LDQ + ncol) * 2;
                uint32_t brh[4], brl[4];
                ldm_x4_trans(brh, vh_s + v_off);
                ldm_x4_trans(brl, vl_s + v_off);
                mma_bf16(oacc[np * 2],     pah, brh);
                mma_bf16(oacc[np * 2],     pah, brl);
                mma_bf16(oacc[np * 2],     pal, brh);
                mma_bf16(oacc[np * 2 + 1], pah, brh + 2);
                mma_bf16(oacc[np * 2 + 1], pah, brl + 2);
                mma_bf16(oacc[np * 2 + 1], pal, brh + 2);
            }
        }
    }

    // write out (split planes)
    float inv[2] = { 1.f / lsum[0], 1.f / lsum[1] };
    size_t gr0 = rowbase + it * 64 + wm * 16 + (lane >> 2);
    #pragma unroll
    for (int j = 0; j < 8; ++j) {
        int col = h * D_ + j * 8 + (lane & 3) * 2;
        #pragma unroll
        for (int rh = 0; rh < 2; ++rh) {
            size_t gr = gr0 + rh * 8;
            float v0 = oacc[j][rh * 2]     * inv[rh];
            float v1 = oacc[j][rh * 2 + 1] * inv[rh];
            split_write2(v0, v1, oh + gr * E_ + col, ol + gr * E_ + col);
        }
    }
}

// ---------------- host launcher ----------------
extern "C" void kernel_launch(void* const* d_in, const int* in_sizes, int n_in,
                              void* d_out, int out_size)
{
    const int*   tokens  = (const int*)  d_in[0];
    const float* tok_emb = (const float*)d_in[1];
    const float* pos_emb = (const float*)d_in[2];
    const float* Wq = (const float*)d_in[3];
    const float* bq = (const float*)d_in[4];
    const float* Wk = (const float*)d_in[5];
    const float* bk = (const float*)d_in[6];
    const float* Wv = (const float*)d_in[7];
    const float* bv = (const float*)d_in[8];
    const float* Wo = (const float*)d_in[9];
    const float* bo = (const float*)d_in[10];
    const float* ln1_g = (const float*)d_in[11];
    const float* ln1_b = (const float*)d_in[12];
    const float* ln2_g = (const float*)d_in[13];
    const float* ln2_b = (const float*)d_in[14];
    const float* W1 = (const float*)d_in[15];
    const float* b1 = (const float*)d_in[16];
    const float* W2 = (const float*)d_in[17];
    const float* b2 = (const float*)d_in[18];
    const float* lnf_g = (const float*)d_in[19];
    const float* lnf_b = (const float*)d_in[20];
    const float* Wf = (const float*)d_in[21];
    const float* bf = (const float*)d_in[22];
    float* out = (float*)d_out;

    float *x, *bqkv;
    __nv_bfloat16 *qkvh, *qkvl, *ahE, *alE, *ahF, *alF;
    __nv_bfloat16 *wqh, *wql, *woh, *wol, *w1h, *w1l, *w2h, *w2l, *wfh, *wfl;
    cudaGetSymbolAddress((void**)&x,    g_x);
    cudaGetSymbolAddress((void**)&bqkv, g_bqkv);
    cudaGetSymbolAddress((void**)&qkvh, g_qkvh);
    cudaGetSymbolAddress((void**)&qkvl, g_qkvl);
    cudaGetSymbolAddress((void**)&ahE,  g_ahE);
    cudaGetSymbolAddress((void**)&alE,  g_alE);
    cudaGetSymbolAddress((void**)&ahF,  g_ahF);
    cudaGetSymbolAddress((void**)&alF,  g_alF);
    cudaGetSymbolAddress((void**)&wqh,  g_wqkv_h);
    cudaGetSymbolAddress((void**)&wql,  g_wqkv_l);
    cudaGetSymbolAddress((void**)&woh,  g_wo_h);
    cudaGetSymbolAddress((void**)&wol,  g_wo_l);
    cudaGetSymbolAddress((void**)&w1h,  g_w1_h);
    cudaGetSymbolAddress((void**)&w1l,  g_w1_l);
    cudaGetSymbolAddress((void**)&w2h,  g_w2_h);
    cudaGetSymbolAddress((void**)&w2l,  g_w2_l);
    cudaGetSymbolAddress((void**)&wfh,  g_wf_h);
    cudaGetSymbolAddress((void**)&wfl,  g_wf_l);

    const size_t EE = (size_t)E_ * E_;
    const int FA_SMEM = 6 * FA_TILE * (int)sizeof(__nv_bfloat16);   // 55296 B
    cudaFuncSetAttribute(flash_kernel, cudaFuncAttributeMaxDynamicSharedMemorySize, FA_SMEM);

    // ---- weight splits ----
    for (int l = 0; l < L_; ++l) {
        size_t qoff = (size_t)l * E_ * QKVN;
        split2_kernel<<<1152, 256>>>((const float4*)(Wq + l * EE),
            (uint2*)(wqh + qoff), (uint2*)(wql + qoff), E_, E_ / 4, QKVN / 4, 0);
        split2_kernel<<<1152, 256>>>((const float4*)(Wk + l * EE),
            (uint2*)(wqh + qoff), (uint2*)(wql + qoff), E_, E_ / 4, QKVN / 4, E_ / 4);
        split2_kernel<<<1152, 256>>>((const float4*)(Wv + l * EE),
            (uint2*)(wqh + qoff), (uint2*)(wql + qoff), E_, E_ / 4, QKVN / 4, 2 * E_ / 4);
        split2_kernel<<<1152, 256>>>((const float4*)(Wo + l * EE),
            (uint2*)(woh + l * EE), (uint2*)(wol + l * EE), E_, E_ / 4, E_ / 4, 0);
        size_t f1 = (size_t)l * E_ * FF_;
        split2_kernel<<<3456, 256>>>((const float4*)(W1 + f1),
            (uint2*)(w1h + f1), (uint2*)(w1l + f1), E_, FF_ / 4, FF_ / 4, 0);
        size_t f2 = (size_t)l * FF_ * E_;
        split2_kernel<<<3456, 256>>>((const float4*)(W2 + f2),
            (uint2*)(w2h + f2), (uint2*)(w2l + f2), FF_, E_ / 4, E_ / 4, 0);
    }
    split2_kernel<<<8192, 256>>>((const float4*)Wf,
        (uint2*)wfh, (uint2*)wfl, E_, V_ / 4, V_ / 4, 0);
    concat_bias_kernel<<<(L_ * QKVN + 255) / 256, 256>>>(bq, bk, bv, bqkv);

    embed_kernel<<<M_, 192>>>(tokens, tok_emb, pos_emb, x);

    dim3 gQKV (M_ / 128, QKVN / 128);   // 16 x 18
    dim3 gProj(M_ / 128, E_ / 128);     // 16 x 6
    dim3 gFF1 (M_ / 128, FF_ / 128);    // 16 x 36
    dim3 gHead(M_ / 128, V_ / 128);     // 16 x 250
    dim3 gFA  (S_ / 64, B_ * H_);       // 16 x 24

    for (int l = 0; l < L_; ++l) {
        size_t qoff = (size_t)l * E_ * QKVN;
        size_t ooff = (size_t)l * EE;
        size_t f1 = (size_t)l * E_ * FF_;
        size_t f2 = (size_t)l * FF_ * E_;

        ln_split_kernel<<<M_, 256>>>(x, ln1_g + l * E_, ln1_b + l * E_, ahE, alE);

        // qkv = h @ Wqkv + b   -> split planes (qkvh, qkvl)
        bgemm2_kernel<2, true, false, false><<<gQKV, 256>>>(
            ahE, alE, wqh + qoff, wql + qoff, bqkv + l * QKVN, nullptr,
            nullptr, qkvh, qkvl, QKVN, E_);

        // o -> split planes
        flash_kernel<<<gFA, 128, FA_SMEM>>>(qkvh, qkvl, ahE, alE);

        // x = x + o @ Wo + bo
        bgemm2_kernel<0, true, true, false><<<gProj, 256>>>(
            ahE, alE, woh + ooff, wol + ooff, bo + l * E_, x,
            x, nullptr, nullptr, E_, E_);

        ln_split_kernel<<<M_, 256>>>(x, ln2_g + l * E_, ln2_b + l * E_, ahE, alE);

        // ff = gelu(h @ W1 + b1) -> split planes
        bgemm2_kernel<2, true, false, true><<<gFF1, 256>>>(
            ahE, alE, w1h + f1, w1l + f1, b1 + l * FF_, nullptr,
            nullptr, ahF, alF, FF_, E_);

        // x = x + ff @ W2 + b2
        bgemm2_kernel<0, true, true, false><<<gProj, 256>>>(
            ahF, alF, w2h + f2, w2l + f2, b2 + l * E_, x,
            x, nullptr, nullptr, E_, FF_);
    }

    ln_split_kernel<<<M_, 256>>>(x, lnf_g, lnf_b, ahE, alE);
    bgemm2_kernel<0, true, false, false><<<gHead, 256>>>(
        ahE, alE, wfh, wfl, bf, nullptr,
        out, nullptr, nullptr, V_, E_);
}

// round 10
// speedup vs baseline: 3.8520x; 1.4060x over previous
#include <cuda_runtime.h>
#include <cuda_bf16.h>
#include <cuda_fp16.h>
#include <math.h>
#include <stdint.h>

// Problem dims (compile-time)
#define E_  768
#define H_  12
#define D_  64
#define L_  4
#define S_  1024
#define B_  2
#define V_  32000
#define FF_ 4608
#define M_  (B_ * S_)   // 2048 rows
#define QKVN 2304       // 3*E

// ---------------- scratch ----------------
__device__ float g_x[M_ * E_];                       // residual stream (fp32)
__device__ float g_bqkv[L_ * QKVN];                  // concatenated qkv bias
__device__ __nv_bfloat16 g_qkvh[(size_t)M_ * QKVN];  // qkv hi plane (bf16, for flash)
__device__ __nv_bfloat16 g_qkvl[(size_t)M_ * QKVN];  // qkv lo plane
// activation split planes (fp16)
__device__ __half g_ahE[(size_t)M_ * E_];
__device__ __half g_alE[(size_t)M_ * E_];
__device__ __half g_ahF[(size_t)M_ * FF_];
__device__ __half g_alF[(size_t)M_ * FF_];
// weights: single fp16 plane
__device__ __half g_wqkv[(size_t)L_ * E_ * QKVN];
__device__ __half g_wo  [(size_t)L_ * E_ * E_];
__device__ __half g_w1  [(size_t)L_ * E_ * FF_];
__device__ __half g_w2  [(size_t)L_ * FF_ * E_];
__device__ __half g_wf  [(size_t)E_ * V_];

// ---------------- small helpers ----------------
__device__ __forceinline__ uint32_t pack_bf2(float a, float b) {
    __nv_bfloat162 t = __floats2bfloat162_rn(a, b);
    return *reinterpret_cast<uint32_t*>(&t);
}
// bf16 split write (flash qkv planes)
__device__ __forceinline__ void split_write2_bf(float v0, float v1,
                                                __nv_bfloat16* ph, __nv_bfloat16* pl) {
    __nv_bfloat16 h0 = __float2bfloat16(v0), h1 = __float2bfloat16(v1);
    __nv_bfloat162 hh; hh.x = h0; hh.y = h1;
    *(__nv_bfloat162*)ph = hh;
    __nv_bfloat162 ll;
    ll.x = __float2bfloat16(v0 - __bfloat162float(h0));
    ll.y = __float2bfloat16(v1 - __bfloat162float(h1));
    *(__nv_bfloat162*)pl = ll;
}
// fp16 split write (activation planes)
__device__ __forceinline__ void split_write2_h(float v0, float v1,
                                               __half* ph, __half* pl) {
    __half h0 = __float2half_rn(v0), h1 = __float2half_rn(v1);
    *(__half2*)ph = __halves2half2(h0, h1);
    *(__half2*)pl = __halves2half2(__float2half_rn(v0 - __half2float(h0)),
                                   __float2half_rn(v1 - __half2float(h1)));
}
// split one float pair into hi/lo packed bf16 regs (flash P split)
__device__ __forceinline__ void split_pack2_bf(float a, float b, uint32_t& hi, uint32_t& lo) {
    __nv_bfloat16 ha = __float2bfloat16(a), hb = __float2bfloat16(b);
    __nv_bfloat162 hh; hh.x = ha; hh.y = hb;
    hi = *reinterpret_cast<uint32_t*>(&hh);
    lo = pack_bf2(a - __bfloat162float(ha), b - __bfloat162float(hb));
}

// ---------------- embedding ----------------
__global__ void embed_kernel(const int* __restrict__ tokens,
                             const float* __restrict__ tok_emb,
                             const float* __restrict__ pos_emb,
                             float* __restrict__ x)
{
    int row = blockIdx.x;
    int s   = row % S_;
    int t   = tokens[row];
    const float4* te = (const float4*)(tok_emb + (size_t)t * E_);
    const float4* pe = (const float4*)(pos_emb + (size_t)s * E_);
    float4*       xo = (float4*)(x + (size_t)row * E_);
    for (int i = threadIdx.x; i < E_ / 4; i += blockDim.x) {
        float4 a = te[i], b = pe[i];
        xo[i] = make_float4(a.x + b.x, a.y + b.y, a.z + b.z, a.w + b.w);
    }
}

// ---------------- layernorm -> fp16 split planes ----------------
__global__ void ln_split_kernel(const float* __restrict__ x,
                                const float* __restrict__ g,
                                const float* __restrict__ b,
                                __half* __restrict__ oh,
                                __half* __restrict__ ol)
{
    int row = blockIdx.x;
    const float* xr = x + (size_t)row * E_;
    __shared__ float red[256];
    int tid = threadIdx.x;

    float s = 0.f;
    for (int i = tid; i < E_; i += 256) s += xr[i];
    red[tid] = s; __syncthreads();
    for (int o = 128; o > 0; o >>= 1) { if (tid < o) red[tid] += red[tid + o]; __syncthreads(); }
    float mean = red[0] * (1.f / E_);
    __syncthreads();

    float sq = 0.f;
    for (int i = tid; i < E_; i += 256) { float d = xr[i] - mean; sq += d * d; }
    red[tid] = sq; __syncthreads();
    for (int o = 128; o > 0; o >>= 1) { if (tid < o) red[tid] += red[tid + o]; __syncthreads(); }
    float inv = rsqrtf(red[0] * (1.f / E_) + 1e-5f);

    __half* ohr = oh + (size_t)row * E_;
    __half* olr = ol + (size_t)row * E_;
    for (int i = tid; i < E_; i += 256) {
        float v = (xr[i] - mean) * inv * g[i] + b[i];
        __half hh = __float2half_rn(v);
        ohr[i] = hh;
        olr[i] = __float2half_rn(v - __half2float(hh));
    }
}

// ---------------- weight convert: W[K,N] fp32 -> fp16 (col offset into wider dst) ----------------
__global__ void convert_kernel(const float4* __restrict__ W,
                               uint2* __restrict__ Wf,
                               int K, int N4, int ld4, int col04)
{
    int total = K * N4;
    for (int idx = blockIdx.x * blockDim.x + threadIdx.x; idx < total;
         idx += gridDim.x * blockDim.x) {
        int k = idx / N4, n = idx - k * N4;
        float4 w = W[idx];
        uint2 hv;
        __half2 p0 = __floats2half2_rn(w.x, w.y);
        __half2 p1 = __floats2half2_rn(w.z, w.w);
        hv.x = *reinterpret_cast<uint32_t*>(&p0);
        hv.y = *reinterpret_cast<uint32_t*>(&p1);
        Wf[(size_t)k * ld4 + col04 + n] = hv;
    }
}

__global__ void concat_bias_kernel(const float* __restrict__ bq,
                                   const float* __restrict__ bk,
                                   const float* __restrict__ bv,
                                   float* __restrict__ bqkv)
{
    int t = blockIdx.x * blockDim.x + threadIdx.x;
    if (t >= L_ * QKVN) return;
    int l = t / QKVN, c = t - l * QKVN;
    float v;
    if (c < E_)           v = bq[l * E_ + c];
    else if (c < 2 * E_)  v = bk[l * E_ + c - E_];
    else                  v = bv[l * E_ + c - 2 * E_];
    bqkv[t] = v;
}

// ---------------- PTX helpers ----------------
__device__ __forceinline__ void cp_async16(uint32_t s, const void* g) {
    asm volatile("cp.async.cg.shared.global [%0], [%1], 16;" :: "r"(s), "l"(g));
}
__device__ __forceinline__ void cp_commit() {
    asm volatile("cp.async.commit_group;");
}
template<int N>
__device__ __forceinline__ void cp_wait() {
    asm volatile("cp.async.wait_group %0;" :: "n"(N));
}
__device__ __forceinline__ void ldm_x4(uint32_t* r, uint32_t addr) {
    asm volatile("ldmatrix.sync.aligned.m8n8.x4.shared.b16 {%0,%1,%2,%3}, [%4];"
                 : "=r"(r[0]), "=r"(r[1]), "=r"(r[2]), "=r"(r[3]) : "r"(addr));
}
__device__ __forceinline__ void ldm_x4_trans(uint32_t* r, uint32_t addr) {
    asm volatile("ldmatrix.sync.aligned.m8n8.x4.trans.shared.b16 {%0,%1,%2,%3}, [%4];"
                 : "=r"(r[0]), "=r"(r[1]), "=r"(r[2]), "=r"(r[3]) : "r"(addr));
}
__device__ __forceinline__ void mma_bf16(float* d, const uint32_t* a, const uint32_t* b) {
    asm volatile(
        "mma.sync.aligned.m16n8k16.row.col.f32.bf16.bf16.f32 "
        "{%0,%1,%2,%3}, {%4,%5,%6,%7}, {%8,%9}, {%0,%1,%2,%3};"
        : "+f"(d[0]), "+f"(d[1]), "+f"(d[2]), "+f"(d[3])
        : "r"(a[0]), "r"(a[1]), "r"(a[2]), "r"(a[3]), "r"(b[0]), "r"(b[1]));
}
__device__ __forceinline__ void mma_f16(float* d, const uint32_t* a, const uint32_t* b) {
    asm volatile(
        "mma.sync.aligned.m16n8k16.row.col.f32.f16.f16.f32 "
        "{%0,%1,%2,%3}, {%4,%5,%6,%7}, {%8,%9}, {%0,%1,%2,%3};"
        : "+f"(d[0]), "+f"(d[1]), "+f"(d[2]), "+f"(d[3])
        : "r"(a[0]), "r"(a[1]), "r"(a[2]), "r"(a[3]), "r"(b[0]), "r"(b[1]));
}

// ---------------- fp16 2-term tensor-core GEMM ----------------
// C[M,N] = Ah@Bf + Al@Bf  (A exact as fp16 pair, B single-rounded fp16).
// blockIdx.x = M tile (fast dim -> B-stripe reuse in L2), blockIdx.y = N tile.
// OUT: 0 = fp32 C (bias/res), 2 = bf16 split planes, 3 = fp16 split planes
template<int OUT, bool BIAS, bool RES, bool GELU>
__global__ void __launch_bounds__(256)
bgemm2_kernel(const __half* __restrict__ Ah, const __half* __restrict__ Al,
              const __half* __restrict__ Bf,
              const float* __restrict__ bias, const float* __restrict__ res,
              float* __restrict__ Cf,
              __nv_bfloat16* __restrict__ Cbh, __nv_bfloat16* __restrict__ Cbl,
              __half* __restrict__ Chh, __half* __restrict__ Chl,
              int Nd, int Kd)
{
    const int LDA = 40;
    const int LDB = 136;
    __shared__ __half As[2][128 * LDA];
    __shared__ __half Bs[2][32 * LDB];

    int tid  = threadIdx.x;
    int lane = tid & 31, wid = tid >> 5;
    int wm = wid & 3, wn = wid >> 2;
    int row0 = blockIdx.x * 128, col0 = blockIdx.y * 128;

    uint32_t asb[2], bsb[2];
    asb[0] = (uint32_t)__cvta_generic_to_shared(&As[0][0]);
    asb[1] = (uint32_t)__cvta_generic_to_shared(&As[1][0]);
    bsb[0] = (uint32_t)__cvta_generic_to_shared(&Bs[0][0]);
    bsb[1] = (uint32_t)__cvta_generic_to_shared(&Bs[1][0]);

    float acc[2][8][4];
    #pragma unroll
    for (int i = 0; i < 2; ++i)
        #pragma unroll
        for (int j = 0; j < 8; ++j)
            #pragma unroll
            for (int t = 0; t < 4; ++t) acc[i][j][t] = 0.f;

    const int KSEG = Kd / 32;
    const int KT   = 2 * KSEG;

    auto load_tile = [&](int buf, int kt) {
        int seg = (kt < KSEG) ? 0 : 1;
        const __half* Ab = seg ? Al : Ah;
        int k0 = (kt - seg * KSEG) * 32;
        #pragma unroll
        for (int i = 0; i < 2; ++i) {
            int chunk = tid * 2 + i;
            int m = chunk >> 2, c = chunk & 3;
            const void* g = Ab + (size_t)(row0 + m) * Kd + k0 + c * 8;
            cp_async16(asb[buf] + (uint32_t)(m * LDA + c * 8) * 2, g);
        }
        #pragma unroll
        for (int i = 0; i < 2; ++i) {
            int chunk = tid * 2 + i;
            int k = chunk >> 4, c = chunk & 15;
            const void* g = Bf + (size_t)(k0 + k) * Nd + col0 + c * 8;
            cp_async16(bsb[buf] + (uint32_t)(k * LDB + c * 8) * 2, g);
        }
        cp_commit();
    };

    load_tile(0, 0);

    for (int kt = 0; kt < KT; ++kt) {
        int buf = kt & 1;
        if (kt + 1 < KT) { load_tile(buf ^ 1, kt + 1); cp_wait<1>(); }
        else             { cp_wait<0>(); }
        __syncthreads();

        #pragma unroll
        for (int kk = 0; kk < 2; ++kk) {
            uint32_t af[2][4];
            #pragma unroll
            for (int mi = 0; mi < 2; ++mi) {
                int m  = wm * 32 + mi * 16 + (lane & 15);
                int kc = kk * 16 + (lane >> 4) * 8;
                ldm_x4(af[mi], asb[buf] + (uint32_t)(m * LDA + kc) * 2);
            }
            uint32_t bfrag[8][2];
            #pragma unroll
            for (int ni4 = 0; ni4 < 4; ++ni4) {
                int g    = lane >> 3;
                int krow = kk * 16 + (g & 1) * 8 + (lane & 7);
                int ncol = wn * 64 + ni4 * 16 + (g >> 1) * 8;
                uint32_t r[4];
                ldm_x4_trans(r, bsb[buf] + (uint32_t)(krow * LDB + ncol) * 2);
                bfrag[2 * ni4][0] = r[0]; bfrag[2 * ni4][1] = r[1];
                bfrag[2 * ni4 + 1][0] = r[2]; bfrag[2 * ni4 + 1][1] = r[3];
            }
            #pragma unroll
            for (int mi = 0; mi < 2; ++mi)
                #pragma unroll
                for (int ni = 0; ni < 8; ++ni)
                    mma_f16(acc[mi][ni], af[mi], bfrag[ni]);
        }
        __syncthreads();
    }

    // epilogue
    #pragma unroll
    for (int mi = 0; mi < 2; ++mi) {
        int r = row0 + wm * 32 + mi * 16 + (lane >> 2);
        #pragma unroll
        for (int ni = 0; ni < 8; ++ni) {
            int c = col0 + wn * 64 + ni * 8 + (lane & 3) * 2;
            float b0 = 0.f, b1 = 0.f;
            if (BIAS) { b0 = bias[c]; b1 = bias[c + 1]; }
            #pragma unroll
            for (int half = 0; half < 2; ++half) {
                int rr = r + half * 8;
                float v0 = acc[mi][ni][half * 2 + 0] + b0;
                float v1 = acc[mi][ni][half * 2 + 1] + b1;
                if (GELU) {
                    v0 = 0.5f * v0 * (1.f + erff(v0 * 0.70710678118654752f));
                    v1 = 0.5f * v1 * (1.f + erff(v1 * 0.70710678118654752f));
                }
                if (RES) {
                    const float2 rv = *(const float2*)(res + (size_t)rr * Nd + c);
                    v0 += rv.x; v1 += rv.y;
                }
                if (OUT == 0) {
                    *(float2*)(Cf + (size_t)rr * Nd + c) = make_float2(v0, v1);
                } else if (OUT == 2) {
                    split_write2_bf(v0, v1, Cbh + (size_t)rr * Nd + c, Cbl + (size_t)rr * Nd + c);
                } else {
                    split_write2_h(v0, v1, Chh + (size_t)rr * Nd + c, Chl + (size_t)rr * Nd + c);
                }
            }
        }
    }
}

// ---------------- flash attention (split-3 bf16 tensor core, online softmax) ----------------
// qkvh/qkvl: [M, 2304] bf16 split planes (q|k|v each 768 = 12 heads x 64).
// S = Qh Kh^T + Qh Kl^T + Ql Kh^T; O += Ph Vh + Ph Vl + Pl Vh.
// Writes o (fp32) split into fp16 (oh, ol) planes at [M, E], cols h*64..h*64+63.
#define LDQ 72
#define FA_TILE (64 * LDQ)
__global__ void __launch_bounds__(128)
flash_kernel(const __nv_bfloat16* __restrict__ qkvh,
             const __nv_bfloat16* __restrict__ qkvl,
             __half* __restrict__ oh, __half* __restrict__ ol)
{
    extern __shared__ __nv_bfloat16 smem[];
    __nv_bfloat16* Qh = smem;
    __nv_bfloat16* Ql = Qh + FA_TILE;
    __nv_bfloat16* Kh = Ql + FA_TILE;
    __nv_bfloat16* Kl = Kh + FA_TILE;
    __nv_bfloat16* Vh = Kl + FA_TILE;
    __nv_bfloat16* Vl = Vh + FA_TILE;

    int it = blockIdx.x;          // q tile
    int z  = blockIdx.y;          // b*H + h
    int b = z / H_, h = z % H_;
    int tid = threadIdx.x, lane = tid & 31, wm = tid >> 5;
    size_t rowbase = (size_t)b * S_;

    // load Q tiles (hi + lo)
    {
        size_t qoff = (rowbase + it * 64) * QKVN + h * D_;
        for (int cc = tid; cc < 512; cc += 128) {
            int r = cc >> 3, c = cc & 7;
            *(uint4*)&Qh[r * LDQ + c * 8] = *(const uint4*)(qkvh + qoff + (size_t)r * QKVN + c * 8);
            *(uint4*)&Ql[r * LDQ + c * 8] = *(const uint4*)(qkvl + qoff + (size_t)r * QKVN + c * 8);
        }
    }
    uint32_t qh_s = (uint32_t)__cvta_generic_to_shared(Qh);
    uint32_t ql_s = (uint32_t)__cvta_generic_to_shared(Ql);
    uint32_t kh_s = (uint32_t)__cvta_generic_to_shared(Kh);
    uint32_t kl_s = (uint32_t)__cvta_generic_to_shared(Kl);
    uint32_t vh_s = (uint32_t)__cvta_generic_to_shared(Vh);
    uint32_t vl_s = (uint32_t)__cvta_generic_to_shared(Vl);

    float oacc[8][4];
    #pragma unroll
    for (int j = 0; j < 8; ++j)
        #pragma unroll
        for (int t = 0; t < 4; ++t) oacc[j][t] = 0.f;
    float m_prev[2] = { -1e30f, -1e30f };
    float lsum[2]   = { 0.f, 0.f };

    for (int jt = 0; jt <= it; ++jt) {
        __syncthreads();
        size_t koff = (rowbase + jt * 64) * QKVN + E_ + h * D_;
        size_t voff = koff + E_;
        for (int cc = tid; cc < 512; cc += 128) {
            int r = cc >> 3, c = cc & 7;
            size_t gr = (size_t)r * QKVN + c * 8;
            int so = r * LDQ + c * 8;
            *(uint4*)&Kh[so] = *(const uint4*)(qkvh + koff + gr);
            *(uint4*)&Kl[so] = *(const uint4*)(qkvl + koff + gr);
            *(uint4*)&Vh[so] = *(const uint4*)(qkvh + voff + gr);
            *(uint4*)&Vl[so] = *(const uint4*)(qkvl + voff + gr);
        }
        __syncthreads();

        // S = Qh Kh + Qh Kl + Ql Kh
        float sacc[8][4];
        #pragma unroll
        for (int j = 0; j < 8; ++j)
            #pragma unroll
            for (int t = 0; t < 4; ++t) sacc[j][t] = 0.f;

        #pragma unroll
        for (int kc = 0; kc < 4; ++kc) {
            uint32_t a_off = (uint32_t)((wm * 16 + (lane & 15)) * LDQ + kc * 16 + (lane >> 4) * 8) * 2;
            uint32_t afh[4], afl[4];
            ldm_x4(afh, qh_s + a_off);
            ldm_x4(afl, ql_s + a_off);
            #pragma unroll
            for (int np = 0; np < 4; ++np) {
                int nrow = np * 16 + (lane & 7) + ((lane >> 4) << 3);
                int ncol = kc * 16 + ((lane >> 3) & 1) * 8;
                uint32_t b_off = (uint32_t)(nrow * LDQ + ncol) * 2;
                uint32_t brh[4], brl[4];
                ldm_x4(brh, kh_s + b_off);
                ldm_x4(brl, kl_s + b_off);
                mma_bf16(sacc[np * 2],     afh, brh);
                mma_bf16(sacc[np * 2],     afh, brl);
                mma_bf16(sacc[np * 2],     afl, brh);
                mma_bf16(sacc[np * 2 + 1], afh, brh + 2);
                mma_bf16(sacc[np * 2 + 1], afh, brl + 2);
                mma_bf16(sacc[np * 2 + 1], afl, brh + 2);
            }
        }

        // scale + causal mask + rowmax
        int rloc = wm * 16 + (lane >> 2);
        float mtile[2] = { -1e30f, -1e30f };
        bool diag = (jt == it);
        #pragma unroll
        for (int j = 0; j < 8; ++j) {
            int cg = jt * 64 + j * 8 + (lane & 3) * 2;
            #pragma unroll
            for (int rh = 0; rh < 2; ++rh) {
                int rg = it * 64 + rloc + rh * 8;
                float s0 = sacc[j][rh * 2]     * 0.125f;
                float s1 = sacc[j][rh * 2 + 1] * 0.125f;
                if (diag) {
                    if (cg     > rg) s0 = -1e30f;
                    if (cg + 1 > rg) s1 = -1e30f;
                }
                sacc[j][rh * 2]     = s0;
                sacc[j][rh * 2 + 1] = s1;
                mtile[rh] = fmaxf(mtile[rh], fmaxf(s0, s1));
            }
        }
        #pragma unroll
        for (int rh = 0; rh < 2; ++rh) {
            mtile[rh] = fmaxf(mtile[rh], __shfl_xor_sync(0xffffffff, mtile[rh], 1));
            mtile[rh] = fmaxf(mtile[rh], __shfl_xor_sync(0xffffffff, mtile[rh], 2));
        }
        float alpha[2];
        #pragma unroll
        for (int rh = 0; rh < 2; ++rh) {
            float mn = fmaxf(m_prev[rh], mtile[rh]);
            alpha[rh] = __expf(m_prev[rh] - mn);
            m_prev[rh] = mn;
        }
        // P = exp(S - m), rowsum
        float rsum[2] = { 0.f, 0.f };
        #pragma unroll
        for (int j = 0; j < 8; ++j)
            #pragma unroll
            for (int rh = 0; rh < 2; ++rh) {
                float p0 = __expf(sacc[j][rh * 2]     - m_prev[rh]);
                float p1 = __expf(sacc[j][rh * 2 + 1] - m_prev[rh]);
                sacc[j][rh * 2] = p0; sacc[j][rh * 2 + 1] = p1;
                rsum[rh] += p0 + p1;
            }
        #pragma unroll
        for (int rh = 0; rh < 2; ++rh) {
            rsum[rh] += __shfl_xor_sync(0xffffffff, rsum[rh], 1);
            rsum[rh] += __shfl_xor_sync(0xffffffff, rsum[rh], 2);
            lsum[rh] = lsum[rh] * alpha[rh] + rsum[rh];
        }
        // rescale O
        #pragma unroll
        for (int j = 0; j < 8; ++j)
            #pragma unroll
            for (int rh = 0; rh < 2; ++rh) {
                oacc[j][rh * 2]     *= alpha[rh];
                oacc[j][rh * 2 + 1] *= alpha[rh];
            }
        // O += Ph Vh + Ph Vl + Pl Vh
        #pragma unroll
        for (int kc = 0; kc < 4; ++kc) {
            uint32_t pah[4], pal[4];
            split_pack2_bf(sacc[2 * kc][0],     sacc[2 * kc][1],     pah[0], pal[0]);
            split_pack2_bf(sacc[2 * kc][2],     sacc[2 * kc][3],     pah[1], pal[1]);
            split_pack2_bf(sacc[2 * kc + 1][0], sacc[2 * kc + 1][1], pah[2], pal[2]);
            split_pack2_bf(sacc[2 * kc + 1][2], sacc[2 * kc + 1][3], pah[3], pal[3]);
            #pragma unroll
            for (int np = 0; np < 4; ++np) {
                int g = lane >> 3;
                int krow = kc * 16 + (g & 1) * 8 + (lane & 7);
                int ncol = np * 16 + (g >> 1) * 8;
                uint32_t v_off = (uint32_t)(krow * LDQ + ncol) * 2;
                uint32_t brh[4], brl[4];
                ldm_x4_trans(brh, vh_s + v_off);
                ldm_x4_trans(brl, vl_s + v_off);
                mma_bf16(oacc[np * 2],     pah, brh);
                mma_bf16(oacc[np * 2],     pah, brl);
                mma_bf16(oacc[np * 2],     pal, brh);
                mma_bf16(oacc[np * 2 + 1], pah, brh + 2);
                mma_bf16(oacc[np * 2 + 1], pah, brl + 2);
                mma_bf16(oacc[np * 2 + 1], pal, brh + 2);
            }
        }
    }

    // write out (fp16 split planes)
    float inv[2] = { 1.f / lsum[0], 1.f / lsum[1] };
    size_t gr0 = rowbase + it * 64 + wm * 16 + (lane >> 2);
    #pragma unroll
    for (int j = 0; j < 8; ++j) {
        int col = h * D_ + j * 8 + (lane & 3) * 2;
        #pragma unroll
        for (int rh = 0; rh < 2; ++rh) {
            size_t gr = gr0 + rh * 8;
            float v0 = oacc[j][rh * 2]     * inv[rh];
            float v1 = oacc[j][rh * 2 + 1] * inv[rh];
            split_write2_h(v0, v1, oh + gr * E_ + col, ol + gr * E_ + col);
        }
    }
}

// ---------------- host launcher ----------------
extern "C" void kernel_launch(void* const* d_in, const int* in_sizes, int n_in,
                              void* d_out, int out_size)
{
    const int*   tokens  = (const int*)  d_in[0];
    const float* tok_emb = (const float*)d_in[1];
    const float* pos_emb = (const float*)d_in[2];
    const float* Wq = (const float*)d_in[3];
    const float* bq = (const float*)d_in[4];
    const float* Wk = (const float*)d_in[5];
    const float* bk = (const float*)d_in[6];
    const float* Wv = (const float*)d_in[7];
    const float* bv = (const float*)d_in[8];
    const float* Wo = (const float*)d_in[9];
    const float* bo = (const float*)d_in[10];
    const float* ln1_g = (const float*)d_in[11];
    const float* ln1_b = (const float*)d_in[12];
    const float* ln2_g = (const float*)d_in[13];
    const float* ln2_b = (const float*)d_in[14];
    const float* W1 = (const float*)d_in[15];
    const float* b1 = (const float*)d_in[16];
    const float* W2 = (const float*)d_in[17];
    const float* b2 = (const float*)d_in[18];
    const float* lnf_g = (const float*)d_in[19];
    const float* lnf_b = (const float*)d_in[20];
    const float* Wf = (const float*)d_in[21];
    const float* bf = (const float*)d_in[22];
    float* out = (float*)d_out;

    float *x, *bqkv;
    __nv_bfloat16 *qkvh, *qkvl;
    __half *ahE, *alE, *ahF, *alF;
    __half *wqkv, *wo, *w1, *w2, *wf;
    cudaGetSymbolAddress((void**)&x,    g_x);
    cudaGetSymbolAddress((void**)&bqkv, g_bqkv);
    cudaGetSymbolAddress((void**)&qkvh, g_qkvh);
    cudaGetSymbolAddress((void**)&qkvl, g_qkvl);
    cudaGetSymbolAddress((void**)&ahE,  g_ahE);
    cudaGetSymbolAddress((void**)&alE,  g_alE);
    cudaGetSymbolAddress((void**)&ahF,  g_ahF);
    cudaGetSymbolAddress((void**)&alF,  g_alF);
    cudaGetSymbolAddress((void**)&wqkv, g_wqkv);
    cudaGetSymbolAddress((void**)&wo,   g_wo);
    cudaGetSymbolAddress((void**)&w1,   g_w1);
    cudaGetSymbolAddress((void**)&w2,   g_w2);
    cudaGetSymbolAddress((void**)&wf,   g_wf);

    const size_t EE = (size_t)E_ * E_;
    const int FA_SMEM = 6 * FA_TILE * (int)sizeof(__nv_bfloat16);   // 55296 B
    cudaFuncSetAttribute(flash_kernel, cudaFuncAttributeMaxDynamicSharedMemorySize, FA_SMEM);

    // ---- weight conversions (fp32 -> fp16, every launch; deterministic) ----
    for (int l = 0; l < L_; ++l) {
        size_t qoff = (size_t)l * E_ * QKVN;
        convert_kernel<<<1152, 256>>>((const float4*)(Wq + l * EE),
            (uint2*)(wqkv + qoff), E_, E_ / 4, QKVN / 4, 0);
        convert_kernel<<<1152, 256>>>((const float4*)(Wk + l * EE),
            (uint2*)(wqkv + qoff), E_, E_ / 4, QKVN / 4, E_ / 4);
        convert_kernel<<<1152, 256>>>((const float4*)(Wv + l * EE),
            (uint2*)(wqkv + qoff), E_, E_ / 4, QKVN / 4, 2 * E_ / 4);
        convert_kernel<<<1152, 256>>>((const float4*)(Wo + l * EE),
            (uint2*)(wo + l * EE), E_, E_ / 4, E_ / 4, 0);
        size_t f1 = (size_t)l * E_ * FF_;
        convert_kernel<<<3456, 256>>>((const float4*)(W1 + f1),
            (uint2*)(w1 + f1), E_, FF_ / 4, FF_ / 4, 0);
        size_t f2 = (size_t)l * FF_ * E_;
        convert_kernel<<<3456, 256>>>((const float4*)(W2 + f2),
            (uint2*)(w2 + f2), FF_, E_ / 4, E_ / 4, 0);
    }
    convert_kernel<<<8192, 256>>>((const float4*)Wf,
        (uint2*)wf, E_, V_ / 4, V_ / 4, 0);
    concat_bias_kernel<<<(L_ * QKVN + 255) / 256, 256>>>(bq, bk, bv, bqkv);

    embed_kernel<<<M_, 192>>>(tokens, tok_emb, pos_emb, x);

    dim3 gQKV (M_ / 128, QKVN / 128);   // 16 x 18
    dim3 gProj(M_ / 128, E_ / 128);     // 16 x 6
    dim3 gFF1 (M_ / 128, FF_ / 128);    // 16 x 36
    dim3 gHead(M_ / 128, V_ / 128);     // 16 x 250
    dim3 gFA  (S_ / 64, B_ * H_);       // 16 x 24

    for (int l = 0; l < L_; ++l) {
        size_t qoff = (size_t)l * E_ * QKVN;
        size_t ooff = (size_t)l * EE;
        size_t f1 = (size_t)l * E_ * FF_;
        size_t f2 = (size_t)l * FF_ * E_;

        ln_split_kernel<<<M_, 256>>>(x, ln1_g + l * E_, ln1_b + l * E_, ahE, alE);

        // qkv = h @ Wqkv + b   -> bf16 split planes (qkvh, qkvl)
        bgemm2_kernel<2, true, false, false><<<gQKV, 256>>>(
            ahE, alE, wqkv + qoff, bqkv + l * QKVN, nullptr,
            nullptr, qkvh, qkvl, nullptr, nullptr, QKVN, E_);

        // o -> fp16 split planes
        flash_kernel<<<gFA, 128, FA_SMEM>>>(qkvh, qkvl, ahE, alE);

        // x = x + o @ Wo + bo
        bgemm2_kernel<0, true, true, false><<<gProj, 256>>>(
            ahE, alE, wo + ooff, bo + l * E_, x,
            x, nullptr, nullptr, nullptr, nullptr, E_, E_);

        ln_split_kernel<<<M_, 256>>>(x, ln2_g + l * E_, ln2_b + l * E_, ahE, alE);

        // ff = gelu(h @ W1 + b1) -> fp16 split planes
        bgemm2_kernel<3, true, false, true><<<gFF1, 256>>>(
            ahE, alE, w1 + f1, b1 + l * FF_, nullptr,
            nullptr, nullptr, nullptr, ahF, alF, FF_, E_);

        // x = x + ff @ W2 + b2
        bgemm2_kernel<0, true, true, false><<<gProj, 256>>>(
            ahF, alF, w2 + f2, b2 + l * E_, x,
            x, nullptr, nullptr, nullptr, nullptr, E_, FF_);
    }

    ln_split_kernel<<<M_, 256>>>(x, lnf_g, lnf_b, ahE, alE);
    bgemm2_kernel<0, true, false, false><<<gHead, 256>>>(
        ahE, alE, wf, bf, nullptr,
        out, nullptr, nullptr, nullptr, nullptr, V_, E_);
}

// round 11
// speedup vs baseline: 4.5354x; 1.1774x over previous
#include <cuda_runtime.h>
#include <cuda_bf16.h>
#include <cuda_fp16.h>
#include <math.h>
#include <stdint.h>

// Problem dims (compile-time)
#define E_  768
#define H_  12
#define D_  64
#define L_  4
#define S_  1024
#define B_  2
#define V_  32000
#define FF_ 4608
#define M_  (B_ * S_)   // 2048 rows
#define QKVN 2304       // 3*E

// ---------------- scratch ----------------
__device__ float g_x[M_ * E_];                       // residual stream (fp32)
__device__ float g_bqkv[L_ * QKVN];                  // concatenated qkv bias
__device__ __nv_bfloat16 g_qkvh[(size_t)M_ * QKVN];  // qkv hi plane (bf16, for flash)
__device__ __nv_bfloat16 g_qkvl[(size_t)M_ * QKVN];  // qkv lo plane
// activation split planes (fp16)
__device__ __half g_ahE[(size_t)M_ * E_];
__device__ __half g_alE[(size_t)M_ * E_];
__device__ __half g_ahF[(size_t)M_ * FF_];
__device__ __half g_alF[(size_t)M_ * FF_];
// weights: single fp16 plane
__device__ __half g_wqkv[(size_t)L_ * E_ * QKVN];
__device__ __half g_wo  [(size_t)L_ * E_ * E_];
__device__ __half g_w1  [(size_t)L_ * E_ * FF_];
__device__ __half g_w2  [(size_t)L_ * FF_ * E_];
__device__ __half g_wf  [(size_t)E_ * V_];

// ---------------- small helpers ----------------
__device__ __forceinline__ uint32_t pack_bf2(float a, float b) {
    __nv_bfloat162 t = __floats2bfloat162_rn(a, b);
    return *reinterpret_cast<uint32_t*>(&t);
}
__device__ __forceinline__ void split_write2_bf(float v0, float v1,
                                                __nv_bfloat16* ph, __nv_bfloat16* pl) {
    __nv_bfloat16 h0 = __float2bfloat16(v0), h1 = __float2bfloat16(v1);
    __nv_bfloat162 hh; hh.x = h0; hh.y = h1;
    *(__nv_bfloat162*)ph = hh;
    __nv_bfloat162 ll;
    ll.x = __float2bfloat16(v0 - __bfloat162float(h0));
    ll.y = __float2bfloat16(v1 - __bfloat162float(h1));
    *(__nv_bfloat162*)pl = ll;
}
__device__ __forceinline__ void split_write2_h(float v0, float v1,
                                               __half* ph, __half* pl) {
    __half h0 = __float2half_rn(v0), h1 = __float2half_rn(v1);
    *(__half2*)ph = __halves2half2(h0, h1);
    *(__half2*)pl = __halves2half2(__float2half_rn(v0 - __half2float(h0)),
                                   __float2half_rn(v1 - __half2float(h1)));
}
__device__ __forceinline__ void split_pack2_bf(float a, float b, uint32_t& hi, uint32_t& lo) {
    __nv_bfloat16 ha = __float2bfloat16(a), hb = __float2bfloat16(b);
    __nv_bfloat162 hh; hh.x = ha; hh.y = hb;
    hi = *reinterpret_cast<uint32_t*>(&hh);
    lo = pack_bf2(a - __bfloat162float(ha), b - __bfloat162float(hb));
}

// ---------------- embedding ----------------
__global__ void embed_kernel(const int* __restrict__ tokens,
                             const float* __restrict__ tok_emb,
                             const float* __restrict__ pos_emb,
                             float* __restrict__ x)
{
    int row = blockIdx.x;
    int s   = row % S_;
    int t   = tokens[row];
    const float4* te = (const float4*)(tok_emb + (size_t)t * E_);
    const float4* pe = (const float4*)(pos_emb + (size_t)s * E_);
    float4*       xo = (float4*)(x + (size_t)row * E_);
    for (int i = threadIdx.x; i < E_ / 4; i += blockDim.x) {
        float4 a = te[i], b = pe[i];
        xo[i] = make_float4(a.x + b.x, a.y + b.y, a.z + b.z, a.w + b.w);
    }
}

// ---------------- layernorm -> fp16 split planes ----------------
__global__ void ln_split_kernel(const float* __restrict__ x,
                                const float* __restrict__ g,
                                const float* __restrict__ b,
                                __half* __restrict__ oh,
                                __half* __restrict__ ol)
{
    int row = blockIdx.x;
    const float* xr = x + (size_t)row * E_;
    __shared__ float red[256];
    int tid = threadIdx.x;

    float s = 0.f;
    for (int i = tid; i < E_; i += 256) s += xr[i];
    red[tid] = s; __syncthreads();
    for (int o = 128; o > 0; o >>= 1) { if (tid < o) red[tid] += red[tid + o]; __syncthreads(); }
    float mean = red[0] * (1.f / E_);
    __syncthreads();

    float sq = 0.f;
    for (int i = tid; i < E_; i += 256) { float d = xr[i] - mean; sq += d * d; }
    red[tid] = sq; __syncthreads();
    for (int o = 128; o > 0; o >>= 1) { if (tid < o) red[tid] += red[tid + o]; __syncthreads(); }
    float inv = rsqrtf(red[0] * (1.f / E_) + 1e-5f);

    __half* ohr = oh + (size_t)row * E_;
    __half* olr = ol + (size_t)row * E_;
    for (int i = tid; i < E_; i += 256) {
        float v = (xr[i] - mean) * inv * g[i] + b[i];
        __half hh = __float2half_rn(v);
        ohr[i] = hh;
        olr[i] = __float2half_rn(v - __half2float(hh));
    }
}

// ---------------- fused weight conversion: all tensors, one launch ----------------
// float4 segment sizes
#define CS0 (L_ * E_ * E_ / 4)      // per tensor: Wq / Wk / Wv / Wo
#define CS1 (L_ * E_ * FF_ / 4)     // W1 / W2
#define CS2 (E_ * V_ / 4)           // Wf
#define CTOTAL (4 * CS0 + 2 * CS1 + CS2)
__global__ void convert_all_kernel(const float4* __restrict__ Wq4, const float4* __restrict__ Wk4,
                                   const float4* __restrict__ Wv4, const float4* __restrict__ Wo4,
                                   const float4* __restrict__ W14, const float4* __restrict__ W24,
                                   const float4* __restrict__ Wf4,
                                   uint2* __restrict__ wqkv_u, uint2* __restrict__ wo_u,
                                   uint2* __restrict__ w1_u, uint2* __restrict__ w2_u,
                                   uint2* __restrict__ wf_u)
{
    for (int idx = blockIdx.x * blockDim.x + threadIdx.x; idx < CTOTAL;
         idx += gridDim.x * blockDim.x) {
        float4 w;
        uint2* dst;
        if (idx < 3 * CS0) {                         // Q|K|V -> interleaved wqkv
            int which = idx / CS0;
            int r = idx - which * CS0;
            const float4* src = (which == 0) ? Wq4 : (which == 1) ? Wk4 : Wv4;
            w = src[r];
            int l  = r / (E_ * E_ / 4);
            int rr = r - l * (E_ * E_ / 4);
            int row = rr / (E_ / 4);
            int n4  = rr - row * (E_ / 4);
            dst = wqkv_u + ((size_t)l * E_ + row) * (QKVN / 4) + which * (E_ / 4) + n4;
        } else if (idx < 4 * CS0) {                  // Wo linear
            int r = idx - 3 * CS0;
            w = Wo4[r]; dst = wo_u + r;
        } else if (idx < 4 * CS0 + CS1) {            // W1 linear
            int r = idx - 4 * CS0;
            w = W14[r]; dst = w1_u + r;
        } else if (idx < 4 * CS0 + 2 * CS1) {        // W2 linear
            int r = idx - 4 * CS0 - CS1;
            w = W24[r]; dst = w2_u + r;
        } else {                                     // Wf linear
            int r = idx - 4 * CS0 - 2 * CS1;
            w = Wf4[r]; dst = wf_u + r;
        }
        __half2 p0 = __floats2half2_rn(w.x, w.y);
        __half2 p1 = __floats2half2_rn(w.z, w.w);
        uint2 hv;
        hv.x = *reinterpret_cast<uint32_t*>(&p0);
        hv.y = *reinterpret_cast<uint32_t*>(&p1);
        *dst = hv;
    }
}

__global__ void concat_bias_kernel(const float* __restrict__ bq,
                                   const float* __restrict__ bk,
                                   const float* __restrict__ bv,
                                   float* __restrict__ bqkv)
{
    int t = blockIdx.x * blockDim.x + threadIdx.x;
    if (t >= L_ * QKVN) return;
    int l = t / QKVN, c = t - l * QKVN;
    float v;
    if (c < E_)           v = bq[l * E_ + c];
    else if (c < 2 * E_)  v = bk[l * E_ + c - E_];
    else                  v = bv[l * E_ + c - 2 * E_];
    bqkv[t] = v;
}

// ---------------- PTX helpers ----------------
__device__ __forceinline__ void cp_async16(uint32_t s, const void* g) {
    asm volatile("cp.async.cg.shared.global [%0], [%1], 16;" :: "r"(s), "l"(g));
}
__device__ __forceinline__ void cp_commit() {
    asm volatile("cp.async.commit_group;");
}
template<int N>
__device__ __forceinline__ void cp_wait() {
    asm volatile("cp.async.wait_group %0;" :: "n"(N));
}
__device__ __forceinline__ void ldm_x4(uint32_t* r, uint32_t addr) {
    asm volatile("ldmatrix.sync.aligned.m8n8.x4.shared.b16 {%0,%1,%2,%3}, [%4];"
                 : "=r"(r[0]), "=r"(r[1]), "=r"(r[2]), "=r"(r[3]) : "r"(addr));
}
__device__ __forceinline__ void ldm_x4_trans(uint32_t* r, uint32_t addr) {
    asm volatile("ldmatrix.sync.aligned.m8n8.x4.trans.shared.b16 {%0,%1,%2,%3}, [%4];"
                 : "=r"(r[0]), "=r"(r[1]), "=r"(r[2]), "=r"(r[3]) : "r"(addr));
}
__device__ __forceinline__ void mma_bf16(float* d, const uint32_t* a, const uint32_t* b) {
    asm volatile(
        "mma.sync.aligned.m16n8k16.row.col.f32.bf16.bf16.f32 "
        "{%0,%1,%2,%3}, {%4,%5,%6,%7}, {%8,%9}, {%0,%1,%2,%3};"
        : "+f"(d[0]), "+f"(d[1]), "+f"(d[2]), "+f"(d[3])
        : "r"(a[0]), "r"(a[1]), "r"(a[2]), "r"(a[3]), "r"(b[0]), "r"(b[1]));
}
__device__ __forceinline__ void mma_f16(float* d, const uint32_t* a, const uint32_t* b) {
    asm volatile(
        "mma.sync.aligned.m16n8k16.row.col.f32.f16.f16.f32 "
        "{%0,%1,%2,%3}, {%4,%5,%6,%7}, {%8,%9}, {%0,%1,%2,%3};"
        : "+f"(d[0]), "+f"(d[1]), "+f"(d[2]), "+f"(d[3])
        : "r"(a[0]), "r"(a[1]), "r"(a[2]), "r"(a[3]), "r"(b[0]), "r"(b[1]));
}

// ---------------- fp16 2-term tensor-core GEMM, 4-stage cp.async pipeline ----------------
// C[M,N] = Ah@Bf + Al@Bf  (A exact as fp16 pair, B single-rounded fp16).
// OUT: 0 = fp32 C (bias/res), 2 = bf16 split planes, 3 = fp16 split planes
#define GLDA 40
#define GLDB 136
#define GSTAGES 4
#define GABYTES (128 * GLDA * 2)
#define GBBYTES (32 * GLDB * 2)
#define GSMEM (GSTAGES * (GABYTES + GBBYTES))   // 75776 B
template<int OUT, bool BIAS, bool RES, bool GELU>
__global__ void __launch_bounds__(256)
bgemm2_kernel(const __half* __restrict__ Ah, const __half* __restrict__ Al,
              const __half* __restrict__ Bf,
              const float* __restrict__ bias, const float* __restrict__ res,
              float* __restrict__ Cf,
              __nv_bfloat16* __restrict__ Cbh, __nv_bfloat16* __restrict__ Cbl,
              __half* __restrict__ Chh, __half* __restrict__ Chl,
              int Nd, int Kd)
{
    extern __shared__ __half dsm[];

    int tid  = threadIdx.x;
    int lane = tid & 31, wid = tid >> 5;
    int wm = wid & 3, wn = wid >> 2;
    int row0 = blockIdx.x * 128, col0 = blockIdx.y * 128;

    uint32_t as0 = (uint32_t)__cvta_generic_to_shared(dsm);
    uint32_t bs0 = as0 + GSTAGES * GABYTES;

    float acc[2][8][4];
    #pragma unroll
    for (int i = 0; i < 2; ++i)
        #pragma unroll
        for (int j = 0; j < 8; ++j)
            #pragma unroll
            for (int t = 0; t < 4; ++t) acc[i][j][t] = 0.f;

    const int KSEG = Kd / 32;
    const int KT   = 2 * KSEG;

    auto load_tile = [&](int buf, int kt) {
        int seg = (kt < KSEG) ? 0 : 1;
        const __half* Ab = seg ? Al : Ah;
        int k0 = (kt - seg * KSEG) * 32;
        uint32_t ab = as0 + buf * GABYTES;
        uint32_t bb = bs0 + buf * GBBYTES;
        #pragma unroll
        for (int i = 0; i < 2; ++i) {
            int chunk = tid * 2 + i;
            int m = chunk >> 2, c = chunk & 3;
            const void* g = Ab + (size_t)(row0 + m) * Kd + k0 + c * 8;
            cp_async16(ab + (uint32_t)(m * GLDA + c * 8) * 2, g);
        }
        #pragma unroll
        for (int i = 0; i < 2; ++i) {
            int chunk = tid * 2 + i;
            int k = chunk >> 4, c = chunk & 15;
            const void* g = Bf + (size_t)(k0 + k) * Nd + col0 + c * 8;
            cp_async16(bb + (uint32_t)(k * GLDB + c * 8) * 2, g);
        }
    };

    // prologue: STAGES-1 groups in flight
    #pragma unroll
    for (int p = 0; p < GSTAGES - 1; ++p) {
        if (p < KT) load_tile(p, p);
        cp_commit();
    }

    for (int kt = 0; kt < KT; ++kt) {
        cp_wait<GSTAGES - 2>();
        __syncthreads();
        int buf = kt & (GSTAGES - 1);
        uint32_t ab = as0 + buf * GABYTES;
        uint32_t bb = bs0 + buf * GBBYTES;

        #pragma unroll
        for (int kk = 0; kk < 2; ++kk) {
            uint32_t af[2][4];
            #pragma unroll
            for (int mi = 0; mi < 2; ++mi) {
                int m  = wm * 32 + mi * 16 + (lane & 15);
                int kc = kk * 16 + (lane >> 4) * 8;
                ldm_x4(af[mi], ab + (uint32_t)(m * GLDA + kc) * 2);
            }
            uint32_t bfrag[8][2];
            #pragma unroll
            for (int ni4 = 0; ni4 < 4; ++ni4) {
                int g    = lane >> 3;
                int krow = kk * 16 + (g & 1) * 8 + (lane & 7);
                int ncol = wn * 64 + ni4 * 16 + (g >> 1) * 8;
                uint32_t r[4];
                ldm_x4_trans(r, bb + (uint32_t)(krow * GLDB + ncol) * 2);
                bfrag[2 * ni4][0] = r[0]; bfrag[2 * ni4][1] = r[1];
                bfrag[2 * ni4 + 1][0] = r[2]; bfrag[2 * ni4 + 1][1] = r[3];
            }
            #pragma unroll
            for (int mi = 0; mi < 2; ++mi)
                #pragma unroll
                for (int ni = 0; ni < 8; ++ni)
                    mma_f16(acc[mi][ni], af[mi], bfrag[ni]);
        }

        int nx = kt + GSTAGES - 1;
        if (nx < KT) load_tile(nx & (GSTAGES - 1), nx);
        cp_commit();
    }

    // epilogue
    #pragma unroll
    for (int mi = 0; mi < 2; ++mi) {
        int r = row0 + wm * 32 + mi * 16 + (lane >> 2);
        #pragma unroll
        for (int ni = 0; ni < 8; ++ni) {
            int c = col0 + wn * 64 + ni * 8 + (lane & 3) * 2;
            float b0 = 0.f, b1 = 0.f;
            if (BIAS) { b0 = bias[c]; b1 = bias[c + 1]; }
            #pragma unroll
            for (int half = 0; half < 2; ++half) {
                int rr = r + half * 8;
                float v0 = acc[mi][ni][half * 2 + 0] + b0;
                float v1 = acc[mi][ni][half * 2 + 1] + b1;
                if (GELU) {
                    v0 = 0.5f * v0 * (1.f + erff(v0 * 0.70710678118654752f));
                    v1 = 0.5f * v1 * (1.f + erff(v1 * 0.70710678118654752f));
                }
                if (RES) {
                    const float2 rv = *(const float2*)(res + (size_t)rr * Nd + c);
                    v0 += rv.x; v1 += rv.y;
                }
                if (OUT == 0) {
                    *(float2*)(Cf + (size_t)rr * Nd + c) = make_float2(v0, v1);
                } else if (OUT == 2) {
                    split_write2_bf(v0, v1, Cbh + (size_t)rr * Nd + c, Cbl + (size_t)rr * Nd + c);
                } else {
                    split_write2_h(v0, v1, Chh + (size_t)rr * Nd + c, Chl + (size_t)rr * Nd + c);
                }
            }
        }
    }
}

// ---------------- flash attention (split-3 bf16 tensor core, online softmax) ----------------
#define LDQ 72
#define FA_TILE (64 * LDQ)
__global__ void __launch_bounds__(128)
flash_kernel(const __nv_bfloat16* __restrict__ qkvh,
             const __nv_bfloat16* __restrict__ qkvl,
             __half* __restrict__ oh, __half* __restrict__ ol)
{
    extern __shared__ __nv_bfloat16 smem[];
    __nv_bfloat16* Qh = smem;
    __nv_bfloat16* Ql = Qh + FA_TILE;
    __nv_bfloat16* Kh = Ql + FA_TILE;
    __nv_bfloat16* Kl = Kh + FA_TILE;
    __nv_bfloat16* Vh = Kl + FA_TILE;
    __nv_bfloat16* Vl = Vh + FA_TILE;

    int it = blockIdx.x;
    int z  = blockIdx.y;
    int b = z / H_, h = z % H_;
    int tid = threadIdx.x, lane = tid & 31, wm = tid >> 5;
    size_t rowbase = (size_t)b * S_;

    {
        size_t qoff = (rowbase + it * 64) * QKVN + h * D_;
        for (int cc = tid; cc < 512; cc += 128) {
            int r = cc >> 3, c = cc & 7;
            *(uint4*)&Qh[r * LDQ + c * 8] = *(const uint4*)(qkvh + qoff + (size_t)r * QKVN + c * 8);
            *(uint4*)&Ql[r * LDQ + c * 8] = *(const uint4*)(qkvl + qoff + (size_t)r * QKVN + c * 8);
        }
    }
    uint32_t qh_s = (uint32_t)__cvta_generic_to_shared(Qh);
    uint32_t ql_s = (uint32_t)__cvta_generic_to_shared(Ql);
    uint32_t kh_s = (uint32_t)__cvta_generic_to_shared(Kh);
    uint32_t kl_s = (uint32_t)__cvta_generic_to_shared(Kl);
    uint32_t vh_s = (uint32_t)__cvta_generic_to_shared(Vh);
    uint32_t vl_s = (uint32_t)__cvta_generic_to_shared(Vl);

    float oacc[8][4];
    #pragma unroll
    for (int j = 0; j < 8; ++j)
        #pragma unroll
        for (int t = 0; t < 4; ++t) oacc[j][t] = 0.f;
    float m_prev[2] = { -1e30f, -1e30f };
    float lsum[2]   = { 0.f, 0.f };

    for (int jt = 0; jt <= it; ++jt) {
        __syncthreads();
        size_t koff = (rowbase + jt * 64) * QKVN + E_ + h * D_;
        size_t voff = koff + E_;
        for (int cc = tid; cc < 512; cc += 128) {
            int r = cc >> 3, c = cc & 7;
            size_t gr = (size_t)r * QKVN + c * 8;
            int so = r * LDQ + c * 8;
            *(uint4*)&Kh[so] = *(const uint4*)(qkvh + koff + gr);
            *(uint4*)&Kl[so] = *(const uint4*)(qkvl + koff + gr);
            *(uint4*)&Vh[so] = *(const uint4*)(qkvh + voff + gr);
            *(uint4*)&Vl[so] = *(const uint4*)(qkvl + voff + gr);
        }
        __syncthreads();

        float sacc[8][4];
        #pragma unroll
        for (int j = 0; j < 8; ++j)
            #pragma unroll
            for (int t = 0; t < 4; ++t) sacc[j][t] = 0.f;

        #pragma unroll
        for (int kc = 0; kc < 4; ++kc) {
            uint32_t a_off = (uint32_t)((wm * 16 + (lane & 15)) * LDQ + kc * 16 + (lane >> 4) * 8) * 2;
            uint32_t afh[4], afl[4];
            ldm_x4(afh, qh_s + a_off);
            ldm_x4(afl, ql_s + a_off);
            #pragma unroll
            for (int np = 0; np < 4; ++np) {
                int nrow = np * 16 + (lane & 7) + ((lane >> 4) << 3);
                int ncol = kc * 16 + ((lane >> 3) & 1) * 8;
                uint32_t b_off = (uint32_t)(nrow * LDQ + ncol) * 2;
                uint32_t brh[4], brl[4];
                ldm_x4(brh, kh_s + b_off);
                ldm_x4(brl, kl_s + b_off);
                mma_bf16(sacc[np * 2],     afh, brh);
                mma_bf16(sacc[np * 2],     afh, brl);
                mma_bf16(sacc[np * 2],     afl, brh);
                mma_bf16(sacc[np * 2 + 1], afh, brh + 2);
                mma_bf16(sacc[np * 2 + 1], afh, brl + 2);
                mma_bf16(sacc[np * 2 + 1], afl, brh + 2);
            }
        }

        int rloc = wm * 16 + (lane >> 2);
        float mtile[2] = { -1e30f, -1e30f };
        bool diag = (jt == it);
        #pragma unroll
        for (int j = 0; j < 8; ++j) {
            int cg = jt * 64 + j * 8 + (lane & 3) * 2;
            #pragma unroll
            for (int rh = 0; rh < 2; ++rh) {
                int rg = it * 64 + rloc + rh * 8;
                float s0 = sacc[j][rh * 2]     * 0.125f;
                float s1 = sacc[j][rh * 2 + 1] * 0.125f;
                if (diag) {
                    if (cg     > rg) s0 = -1e30f;
                    if (cg + 1 > rg) s1 = -1e30f;
                }
                sacc[j][rh * 2]     = s0;
                sacc[j][rh * 2 + 1] = s1;
                mtile[rh] = fmaxf(mtile[rh], fmaxf(s0, s1));
            }
        }
        #pragma unroll
        for (int rh = 0; rh < 2; ++rh) {
            mtile[rh] = fmaxf(mtile[rh], __shfl_xor_sync(0xffffffff, mtile[rh], 1));
            mtile[rh] = fmaxf(mtile[rh], __shfl_xor_sync(0xffffffff, mtile[rh], 2));
        }
        float alpha[2];
        #pragma unroll
        for (int rh = 0; rh < 2; ++rh) {
            float mn = fmaxf(m_prev[rh], mtile[rh]);
            alpha[rh] = __expf(m_prev[rh] - mn);
            m_prev[rh] = mn;
        }
        float rsum[2] = { 0.f, 0.f };
        #pragma unroll
        for (int j = 0; j < 8; ++j)
            #pragma unroll
            for (int rh = 0; rh < 2; ++rh) {
                float p0 = __expf(sacc[j][rh * 2]     - m_prev[rh]);
                float p1 = __expf(sacc[j][rh * 2 + 1] - m_prev[rh]);
                sacc[j][rh * 2] = p0; sacc[j][rh * 2 + 1] = p1;
                rsum[rh] += p0 + p1;
            }
        #pragma unroll
        for (int rh = 0; rh < 2; ++rh) {
            rsum[rh] += __shfl_xor_sync(0xffffffff, rsum[rh], 1);
            rsum[rh] += __shfl_xor_sync(0xffffffff, rsum[rh], 2);
            lsum[rh] = lsum[rh] * alpha[rh] + rsum[rh];
        }
        #pragma unroll
        for (int j = 0; j < 8; ++j)
            #pragma unroll
            for (int rh = 0; rh < 2; ++rh) {
                oacc[j][rh * 2]     *= alpha[rh];
                oacc[j][rh * 2 + 1] *= alpha[rh];
            }
        #pragma unroll
        for (int kc = 0; kc < 4; ++kc) {
            uint32_t pah[4], pal[4];
            split_pack2_bf(sacc[2 * kc][0],     sacc[2 * kc][1],     pah[0], pal[0]);
            split_pack2_bf(sacc[2 * kc][2],     sacc[2 * kc][3],     pah[1], pal[1]);
            split_pack2_bf(sacc[2 * kc + 1][0], sacc[2 * kc + 1][1], pah[2], pal[2]);
            split_pack2_bf(sacc[2 * kc + 1][2], sacc[2 * kc + 1][3], pah[3], pal[3]);
            #pragma unroll
            for (int np = 0; np < 4; ++np) {
                int g = lane >> 3;
                int krow = kc * 16 + (g & 1) * 8 + (lane & 7);
                int ncol = np * 16 + (g >> 1) * 8;
                uint32_t v_off = (uint32_t)(krow * LDQ + ncol) * 2;
                uint32_t brh[4], brl[4];
                ldm_x4_trans(brh, vh_s + v_off);
                ldm_x4_trans(brl, vl_s + v_off);
                mma_bf16(oacc[np * 2],     pah, brh);
                mma_bf16(oacc[np * 2],     pah, brl);
                mma_bf16(oacc[np * 2],     pal, brh);
                mma_bf16(oacc[np * 2 + 1], pah, brh + 2);
                mma_bf16(oacc[np * 2 + 1], pah, brl + 2);
                mma_bf16(oacc[np * 2 + 1], pal, brh + 2);
            }
        }
    }

    float inv[2] = { 1.f / lsum[0], 1.f / lsum[1] };
    size_t gr0 = rowbase + it * 64 + wm * 16 + (lane >> 2);
    #pragma unroll
    for (int j = 0; j < 8; ++j) {
        int col = h * D_ + j * 8 + (lane & 3) * 2;
        #pragma unroll
        for (int rh = 0; rh < 2; ++rh) {
            size_t gr = gr0 + rh * 8;
            float v0 = oacc[j][rh * 2]     * inv[rh];
            float v1 = oacc[j][rh * 2 + 1] * inv[rh];
            split_write2_h(v0, v1, oh + gr * E_ + col, ol + gr * E_ + col);
        }
    }
}

// ---------------- host launcher ----------------
extern "C" void kernel_launch(void* const* d_in, const int* in_sizes, int n_in,
                              void* d_out, int out_size)
{
    const int*   tokens  = (const int*)  d_in[0];
    const float* tok_emb = (const float*)d_in[1];
    const float* pos_emb = (const float*)d_in[2];
    const float* Wq = (const float*)d_in[3];
    const float* bq = (const float*)d_in[4];
    const float* Wk = (const float*)d_in[5];
    const float* bk = (const float*)d_in[6];
    const float* Wv = (const float*)d_in[7];
    const float* bv = (const float*)d_in[8];
    const float* Wo = (const float*)d_in[9];
    const float* bo = (const float*)d_in[10];
    const float* ln1_g = (const float*)d_in[11];
    const float* ln1_b = (const float*)d_in[12];
    const float* ln2_g = (const float*)d_in[13];
    const float* ln2_b = (const float*)d_in[14];
    const float* W1 = (const float*)d_in[15];
    const float* b1 = (const float*)d_in[16];
    const float* W2 = (const float*)d_in[17];
    const float* b2 = (const float*)d_in[18];
    const float* lnf_g = (const float*)d_in[19];
    const float* lnf_b = (const float*)d_in[20];
    const float* Wf = (const float*)d_in[21];
    const float* bf = (const float*)d_in[22];
    float* out = (float*)d_out;

    float *x, *bqkv;
    __nv_bfloat16 *qkvh, *qkvl;
    __half *ahE, *alE, *ahF, *alF;
    __half *wqkv, *wo, *w1, *w2, *wf;
    cudaGetSymbolAddress((void**)&x,    g_x);
    cudaGetSymbolAddress((void**)&bqkv, g_bqkv);
    cudaGetSymbolAddress((void**)&qkvh, g_qkvh);
    cudaGetSymbolAddress((void**)&qkvl, g_qkvl);
    cudaGetSymbolAddress((void**)&ahE,  g_ahE);
    cudaGetSymbolAddress((void**)&alE,  g_alE);
    cudaGetSymbolAddress((void**)&ahF,  g_ahF);
    cudaGetSymbolAddress((void**)&alF,  g_alF);
    cudaGetSymbolAddress((void**)&wqkv, g_wqkv);
    cudaGetSymbolAddress((void**)&wo,   g_wo);
    cudaGetSymbolAddress((void**)&w1,   g_w1);
    cudaGetSymbolAddress((void**)&w2,   g_w2);
    cudaGetSymbolAddress((void**)&wf,   g_wf);

    const size_t EE = (size_t)E_ * E_;
    const int FA_SMEM = 6 * FA_TILE * (int)sizeof(__nv_bfloat16);   // 55296 B
    cudaFuncSetAttribute(flash_kernel, cudaFuncAttributeMaxDynamicSharedMemorySize, FA_SMEM);
    cudaFuncSetAttribute(bgemm2_kernel<2, true, false, false>,
                         cudaFuncAttributeMaxDynamicSharedMemorySize, GSMEM);
    cudaFuncSetAttribute(bgemm2_kernel<0, true, true, false>,
                         cudaFuncAttributeMaxDynamicSharedMemorySize, GSMEM);
    cudaFuncSetAttribute(bgemm2_kernel<3, true, false, true>,
                         cudaFuncAttributeMaxDynamicSharedMemorySize, GSMEM);
    cudaFuncSetAttribute(bgemm2_kernel<0, true, false, false>,
                         cudaFuncAttributeMaxDynamicSharedMemorySize, GSMEM);

    // ---- fused weight conversion (one launch) ----
    convert_all_kernel<<<4096, 256>>>(
        (const float4*)Wq, (const float4*)Wk, (const float4*)Wv, (const float4*)Wo,
        (const float4*)W1, (const float4*)W2, (const float4*)Wf,
        (uint2*)wqkv, (uint2*)wo, (uint2*)w1, (uint2*)w2, (uint2*)wf);
    concat_bias_kernel<<<(L_ * QKVN + 255) / 256, 256>>>(bq, bk, bv, bqkv);

    embed_kernel<<<M_, 192>>>(tokens, tok_emb, pos_emb, x);

    dim3 gQKV (M_ / 128, QKVN / 128);   // 16 x 18
    dim3 gProj(M_ / 128, E_ / 128);     // 16 x 6
    dim3 gFF1 (M_ / 128, FF_ / 128);    // 16 x 36
    dim3 gHead(M_ / 128, V_ / 128);     // 16 x 250
    dim3 gFA  (S_ / 64, B_ * H_);       // 16 x 24

    for (int l = 0; l < L_; ++l) {
        size_t qoff = (size_t)l * E_ * QKVN;
        size_t ooff = (size_t)l * EE;
        size_t f1 = (size_t)l * E_ * FF_;
        size_t f2 = (size_t)l * FF_ * E_;

        ln_split_kernel<<<M_, 256>>>(x, ln1_g + l * E_, ln1_b + l * E_, ahE, alE);

        // qkv = h @ Wqkv + b   -> bf16 split planes (qkvh, qkvl)
        bgemm2_kernel<2, true, false, false><<<gQKV, 256, GSMEM>>>(
            ahE, alE, wqkv + qoff, bqkv + l * QKVN, nullptr,
            nullptr, qkvh, qkvl, nullptr, nullptr, QKVN, E_);

        // o -> fp16 split planes
        flash_kernel<<<gFA, 128, FA_SMEM>>>(qkvh, qkvl, ahE, alE);

        // x = x + o @ Wo + bo
        bgemm2_kernel<0, true, true, false><<<gProj, 256, GSMEM>>>(
            ahE, alE, wo + ooff, bo + l * E_, x,
            x, nullptr, nullptr, nullptr, nullptr, E_, E_);

        ln_split_kernel<<<M_, 256>>>(x, ln2_g + l * E_, ln2_b + l * E_, ahE, alE);

        // ff = gelu(h @ W1 + b1) -> fp16 split planes
        bgemm2_kernel<3, true, false, true><<<gFF1, 256, GSMEM>>>(
            ahE, alE, w1 + f1, b1 + l * FF_, nullptr,
            nullptr, nullptr, nullptr, ahF, alF, FF_, E_);

        // x = x + ff @ W2 + b2
        bgemm2_kernel<0, true, true, false><<<gProj, 256, GSMEM>>>(
            ahF, alF, w2 + f2, b2 + l * E_, x,
            x, nullptr, nullptr, nullptr, nullptr, E_, FF_);
    }

    ln_split_kernel<<<M_, 256>>>(x, lnf_g, lnf_b, ahE, alE);
    bgemm2_kernel<0, true, false, false><<<gHead, 256, GSMEM>>>(
        ahE, alE, wf, bf, nullptr,
        out, nullptr, nullptr, nullptr, nullptr, V_, E_);
}